// round 11
// baseline (speedup 1.0000x reference)
#include <cuda_runtime.h>
#include <cuda_bf16.h>
#include <cstdint>
#include <math.h>

// Problem constants
#define BB 4
#define TT 512
#define DD 512
#define HH 1024
#define VV 50000
#define VPAD 50048             // VV rounded up to 128
#define NTILE (VPAD/128)       // 391 n-tiles in the V GEMM
#define PSPITCH 392            // partial-sum row pitch
#define MROWS (BB*TT)          // 2048
#define G4H (4*HH)             // 4096
#define NB_REC 128             // recurrence CTAs (all resident wave-1)
#define NCHUNK 16              // h broadcast chunks per step (64 cols each)
#define CPC 8                  // CTAs per chunk
#define CNT_TARGET (CPC*32)    // 8 CTAs x 32 lanes release per chunk
#define HSP 136                // hstage bf16 row pitch (bank-conflict-light)

// ---------------- device scratch (static; zero-initialized) ------------------
__device__ __align__(256) __nv_bfloat16 g_emb [MROWS*DD];
__device__ __align__(256) __nv_bfloat16 g_Wih0[G4H*DD];
__device__ __align__(256) __nv_bfloat16 g_Wout[(size_t)VPAD*HH];  // tail rows stay 0
__device__ __align__(256) float         g_xg  [MROWS*G4H];
__device__ __align__(256) __nv_bfloat16 g_h1  [MROWS*HH];
__device__ __align__(256) __nv_bfloat16 g_h0buf[2*BB*HH];         // bf16 h0 exchange
__device__ __align__(256) __nv_bfloat16 g_h1buf[2*BB*HH];         // bf16 h1 exchange
__device__ __align__(256) int           g_cnt0[TT][NCHUNK][32];   // counter @[..][0]
__device__ __align__(256) int           g_cnt1[TT][NCHUNK][32];
__device__ __align__(256) float         g_psum[(size_t)MROWS*PSPITCH];
__device__ __align__(256) float         g_rowoff[MROWS];

// ---------------- small helpers ----------------------------------------------
__device__ __forceinline__ uint32_t smem_u32(const void* p) {
    return (uint32_t)__cvta_generic_to_shared(p);
}
__device__ __forceinline__ void ldmatrix_x4(uint32_t r[4], uint32_t addr) {
    asm volatile("ldmatrix.sync.aligned.m8n8.x4.shared.b16 {%0,%1,%2,%3}, [%4];"
                 : "=r"(r[0]), "=r"(r[1]), "=r"(r[2]), "=r"(r[3]) : "r"(addr));
}
__device__ __forceinline__ void ldmatrix_x2(uint32_t r[2], uint32_t addr) {
    asm volatile("ldmatrix.sync.aligned.m8n8.x2.shared.b16 {%0,%1}, [%2];"
                 : "=r"(r[0]), "=r"(r[1]) : "r"(addr));
}
__device__ __forceinline__ void mma16816(float d[4], const uint32_t a[4],
                                         const uint32_t b[2], const float c[4]) {
    asm volatile(
        "mma.sync.aligned.m16n8k16.row.col.f32.bf16.bf16.f32 "
        "{%0,%1,%2,%3}, {%4,%5,%6,%7}, {%8,%9}, {%10,%11,%12,%13};"
        : "=f"(d[0]), "=f"(d[1]), "=f"(d[2]), "=f"(d[3])
        : "r"(a[0]), "r"(a[1]), "r"(a[2]), "r"(a[3]),
          "r"(b[0]), "r"(b[1]),
          "f"(c[0]), "f"(c[1]), "f"(c[2]), "f"(c[3]));
}
__device__ __forceinline__ void cp_async16(uint32_t saddr, const void* g) {
    asm volatile("cp.async.cg.shared.global [%0], [%1], 16;" :: "r"(saddr), "l"(g));
}
__device__ __forceinline__ void cp_commit() {
    asm volatile("cp.async.commit_group;");
}
__device__ __forceinline__ int ld_acq(const int* p) {
    int v;
    asm volatile("ld.acquire.gpu.global.b32 %0, [%1];" : "=r"(v) : "l"(p) : "memory");
    return v;
}
__device__ __forceinline__ void red_rel_add(int* p) {
    int one = 1;
    asm volatile("red.release.gpu.global.add.s32 [%0], %1;" :: "l"(p), "r"(one) : "memory");
}
__device__ __forceinline__ float tanhapx(float x) {
    float y; asm("tanh.approx.f32 %0, %1;" : "=f"(y) : "f"(x)); return y;
}
__device__ __forceinline__ float sigapx(float x) {
    return fmaf(0.5f, tanhapx(0.5f * x), 0.5f);
}
__device__ __forceinline__ uint32_t pack_bf2(float x, float y) {
    __nv_bfloat162 b = __floats2bfloat162_rn(x, y);   // .x in low half
    return *(uint32_t*)&b;
}
__device__ __forceinline__ uint32_t lds_u32(uint32_t addr) {
    uint32_t v;
    asm volatile("ld.shared.b32 %0, [%1];" : "=r"(v) : "r"(addr));
    return v;
}

// ---------------- conversion / gather kernels ---------------------------------
__global__ void f32_to_bf16_k(const float* __restrict__ in,
                              __nv_bfloat16* __restrict__ out, int n4) {
    int i = blockIdx.x * blockDim.x + threadIdx.x;
    if (i >= n4) return;
    float4 v = *((const float4*)in + i);
    __nv_bfloat162 lo = __floats2bfloat162_rn(v.x, v.y);
    __nv_bfloat162 hi = __floats2bfloat162_rn(v.z, v.w);
    uint2 u;
    u.x = *(uint32_t*)&lo; u.y = *(uint32_t*)&hi;
    *((uint2*)out + i) = u;
}

__global__ void gather_embed_k(const int* __restrict__ idx,
                               const float* __restrict__ X) {
    int i = blockIdx.x * blockDim.x + threadIdx.x;   // one float4 each
    if (i >= MROWS * (DD/4)) return;
    int r = i >> 7;             // DD/4 = 128
    int j = i & 127;
    int tok = __ldg(&idx[r]);
    float4 v = *(const float4*)(X + (size_t)tok * DD + j * 4);
    __nv_bfloat162 lo = __floats2bfloat162_rn(v.x, v.y);
    __nv_bfloat162 hi = __floats2bfloat162_rn(v.z, v.w);
    uint2 u; u.x = *(uint32_t*)&lo; u.y = *(uint32_t*)&hi;
    *((uint2*)(g_emb + (size_t)r * DD) + j) = u;
}

// ---------------- bf16 MMA GEMM: C[M,N] = A[M,K] * B[N,K]^T + bias ------------
// CTA tile 128x128, K-tile 32, cp.async 5-stage pipeline (4 groups in flight),
// 8 warps (2Mx4N, warp tile 64x32).
// do_sum: also emit per-tile exp-row-sums into psum[row*PSPITCH + blockIdx.y].
#define GPITCH 40
#define GSTAGE (128*GPITCH)                 // bf16 elems per matrix per stage
#define NSTAGE 5
#define GEMM_SMEM (NSTAGE*2*GSTAGE*2)       // bytes = 102400

__global__ __launch_bounds__(256) void gemm_bf16_k(
    const __nv_bfloat16* __restrict__ A, const __nv_bfloat16* __restrict__ B,
    const float* __restrict__ bias, float* __restrict__ C,
    int M, int N, int K, float* __restrict__ psum, int do_sum)
{
    extern __shared__ __nv_bfloat16 gsm_[];

    const int tid  = threadIdx.x;
    const int warp = tid >> 5, lane = tid & 31;
    const int wm = warp & 1, wn = warp >> 1;
    const int m0 = blockIdx.x * 128, n0 = blockIdx.y * 128;

    float acc[4][4][4];
#pragma unroll
    for (int a = 0; a < 4; a++)
#pragma unroll
        for (int b = 0; b < 4; b++)
#pragma unroll
            for (int c = 0; c < 4; c++) acc[a][b][c] = 0.f;

    const int ktiles = K >> 5;              // K-tile = 32 (>= 16 always here)

    // stage loader: 128 rows x 32 cols of A and B (one 16B chunk x2 per thread pass)
    auto load_stage = [&](int st, int k0) {
        __nv_bfloat16* sA = gsm_ + st * 2 * GSTAGE;
        __nv_bfloat16* sB = sA + GSTAGE;
#pragma unroll
        for (int i = 0; i < 2; i++) {
            int c   = tid + i * 256;        // 512 chunks
            int row = c >> 2;
            int col = (c & 3) << 3;
            cp_async16(smem_u32(sA + row*GPITCH + col),
                       A + (size_t)(m0 + row) * K + k0 + col);
            cp_async16(smem_u32(sB + row*GPITCH + col),
                       B + (size_t)(n0 + row) * K + k0 + col);
        }
    };

    // prologue: 4 stages in flight
#pragma unroll
    for (int s = 0; s < 4; s++) { load_stage(s, s << 5); cp_commit(); }

    int st = 0;
    for (int kt = 0; kt < ktiles; kt++) {
        // wait until group kt is complete (keep 'rem' newer groups pending)
        int rem = ktiles - 1 - kt;
        if (rem >= 3)      asm volatile("cp.async.wait_group 3;");
        else if (rem == 2) asm volatile("cp.async.wait_group 2;");
        else if (rem == 1) asm volatile("cp.async.wait_group 1;");
        else               asm volatile("cp.async.wait_group 0;");
        __syncthreads();

        // prefetch stage kt+4 into the slot consumed at kt-1
        if (kt + 4 < ktiles) {
            int st4 = st + 4; if (st4 >= NSTAGE) st4 -= NSTAGE;
            load_stage(st4, (kt + 4) << 5);
            cp_commit();
        }

        const __nv_bfloat16* cA = gsm_ + st * 2 * GSTAGE;
        const __nv_bfloat16* cB = cA + GSTAGE;
#pragma unroll
        for (int ks = 0; ks < 2; ks++) {
            uint32_t af[4][4], bf[4][2];
#pragma unroll
            for (int mt = 0; mt < 4; mt++) {
                uint32_t addr = smem_u32(
                    cA + (wm*64 + mt*16 + (lane & 15))*GPITCH
                       + ks*16 + ((lane >> 4) << 3));
                ldmatrix_x4(af[mt], addr);
            }
#pragma unroll
            for (int nt = 0; nt < 4; nt++) {
                uint32_t addr = smem_u32(
                    cB + (wn*32 + nt*8 + (lane & 7))*GPITCH
                       + ks*16 + (((lane >> 3) & 1) << 3));
                ldmatrix_x2(bf[nt], addr);
            }
#pragma unroll
            for (int mt = 0; mt < 4; mt++)
#pragma unroll
                for (int nt = 0; nt < 4; nt++)
                    mma16816(acc[mt][nt], af[mt], bf[nt], acc[mt][nt]);
        }
        __syncthreads();
        if (++st == NSTAGE) st = 0;
    }

    // epilogue: write C (+ optional exp-row-sum partials)
    float rs[4][2];
#pragma unroll
    for (int mt = 0; mt < 4; mt++) { rs[mt][0] = 0.f; rs[mt][1] = 0.f; }

#pragma unroll
    for (int mt = 0; mt < 4; mt++)
#pragma unroll
        for (int nt = 0; nt < 4; nt++)
#pragma unroll
            for (int i = 0; i < 4; i++) {
                int row = m0 + wm*64 + mt*16 + (lane >> 2) + ((i >> 1) << 3);
                int col = n0 + wn*32 + nt*8 + ((lane & 3) << 1) + (i & 1);
                if (col < N) {
                    float v = acc[mt][nt][i] + __ldg(&bias[col]);
                    C[(size_t)row * N + col] = v;
                    if (do_sum) rs[mt][i >> 1] += __expf(v);
                }
            }

    if (do_sum) {
        float* ps = (float*)gsm_;            // [4][128] floats, reuse smem
        __syncthreads();
#pragma unroll
        for (int mt = 0; mt < 4; mt++)
#pragma unroll
            for (int ih = 0; ih < 2; ih++) {
                float s = rs[mt][ih];
                s += __shfl_xor_sync(0xffffffffu, s, 1);
                s += __shfl_xor_sync(0xffffffffu, s, 2);
                if ((lane & 3) == 0) {
                    int rloc = wm*64 + mt*16 + (lane >> 2) + ih*8;
                    ps[wn*128 + rloc] = s;
                }
            }
        __syncthreads();
        if (tid < 128) {
            float s = ps[tid] + ps[128 + tid] + ps[256 + tid] + ps[384 + tid];
            psum[(size_t)(m0 + tid) * PSPITCH + blockIdx.y] = s;
        }
    }
}

// ---------------- fused 2-layer persistent LSTM -------------------------------
// 128 CTAs x 256 threads, TT+1 pipelined waves. Wave s computes layer0 step s
// (if s<TT) and layer1 step s-1 (if s>=1); both consume data published in
// wave s-1. Per CTA: 32 gate rows per layer; warp ke owns k-slice
// [128ke,128ke+128) with register A-fragments for W_hh0, W_ih1, W_hh1.
// W_ih1@h0 and W_hh1@h1 share one accumulator (acc1). Warp0 tail publishes
// h0 -> cnt0; warp1 tail publishes h1 -> cnt1 (chunk counters, defer-2 recycle).
__global__ __launch_bounds__(256) void lstm_fused_k(
    const float* __restrict__ xg,
    const float* __restrict__ Whh0,
    const float* __restrict__ Wih1,
    const float* __restrict__ b1,
    const float* __restrict__ Whh1,
    __nv_bfloat16* __restrict__ hseq1)
{
    __shared__ __align__(16) __nv_bfloat16 hst0[8][4][HSP];  // staged h0 per warp
    __shared__ __align__(16) __nv_bfloat16 hst1[8][4][HSP];  // staged h1 per warp
    __shared__ __align__(16) float part0[8*128];
    __shared__ __align__(16) float part1[8*128];
    __shared__ float sxg[2][128];
    __shared__ float csm0[32], csm1[32];

    const int tid  = threadIdx.x;
    const int bk   = blockIdx.x;
    const int c0   = bk * 8;
    const int ke   = tid >> 5;
    const int lane = tid & 31;

    // clear counter slots a previous replay left set
    if (bk < NCHUNK && tid == 0) {
        g_cnt0[TT-2][bk][0] = 0; g_cnt0[TT-1][bk][0] = 0;
        g_cnt1[TT-2][bk][0] = 0; g_cnt1[TT-1][bk][0] = 0;
    }

    // ---- preload 3 weight sets as m16n8k16 A-fragments (fp32 -> bf16) ----
    uint32_t A0[2][8][4], Ai[2][8][4], A1[2][8][4];
    {
        const int r0 = lane >> 2;
        const int kc = (lane & 3) * 2;
#pragma unroll
        for (int mt = 0; mt < 2; mt++) {
#pragma unroll
            for (int kt = 0; kt < 8; kt++) {
                int kg = 128*ke + 16*kt + kc;
                int lrA = 16*mt + r0, lrB = lrA + 8;
                size_t oA = (size_t)((lrA >> 3)*HH + c0 + (lrA & 7)) * HH + kg;
                size_t oB = (size_t)((lrB >> 3)*HH + c0 + (lrB & 7)) * HH + kg;
#define LOADFRAG(W, F) { \
                float2 a0 = __ldg((const float2*)(W + oA)); \
                float2 a1 = __ldg((const float2*)(W + oB)); \
                float2 a2 = __ldg((const float2*)(W + oA + 8)); \
                float2 a3 = __ldg((const float2*)(W + oB + 8)); \
                F[mt][kt][0] = pack_bf2(a0.x, a0.y); \
                F[mt][kt][1] = pack_bf2(a1.x, a1.y); \
                F[mt][kt][2] = pack_bf2(a2.x, a2.y); \
                F[mt][kt][3] = pack_bf2(a3.x, a3.y); }
                LOADFRAG(Whh0, A0)
                LOADFRAG(Wih1, Ai)
                LOADFRAG(Whh1, A1)
#undef LOADFRAG
            }
        }
    }
    if (tid < 32) { csm0[tid] = 0.f; csm1[tid] = 0.f; }

    // warp1 tail: bias b1 for its 4 gates (cell cc = lane>>2)
    float b1v[4];
    {
        int cc = lane >> 2;
#pragma unroll
        for (int g = 0; g < 4; g++) b1v[g] = __ldg(&b1[g*HH + c0 + cc]);
    }

    // xg loader mapping (tid < 128): lr = tid>>2, b = tid&3
    const int lrx = tid >> 2, bx = tid & 3;
    const float* xgp = xg + (size_t)bx*TT*G4H + (lrx >> 3)*HH + c0 + (lrx & 7);

    // B-fragment read setup: n = lane>>2 (batch; >=4 -> zero)
    const int  bsel = (lane >> 2) & 3;
    const bool bval = lane < 16;
    const uint32_t hb0 = smem_u32(&hst0[ke][bsel][0]) + (lane & 3) * 4;
    const uint32_t hb1 = smem_u32(&hst1[ke][bsel][0]) + (lane & 3) * 4;
    const int sb = lane >> 3, sj = (lane & 7) * 8;   // stage store mapping

    __syncthreads();

    for (int s = 0; s <= TT; s++) {
        if (tid < 128 && s < TT) sxg[s & 1][tid] = __ldg(xgp + (size_t)s * G4H);

        float acc0[8] = {0,0,0,0,0,0,0,0};   // layer0 gates (2 m-tiles x 4)
        float acc1[8] = {0,0,0,0,0,0,0,0};   // layer1 gates

        if (s > 0) {
            const __nv_bfloat16* h0src = g_h0buf + (s & 1) * BB * HH;
            const __nv_bfloat16* h1src = g_h1buf + (s & 1) * BB * HH;
#pragma unroll
            for (int half = 0; half < 2; half++) {
                const int ch = 2*ke + half;
                // --- h0 chunk: feeds W_hh0 (acc0) and W_ih1 (acc1) ---
                {
                    const int* cp = &g_cnt0[s-1][ch][0];
                    int v; do { v = ld_acq(cp); } while (v < CNT_TARGET);
                    uint4 hv = __ldcg((const uint4*)(h0src + sb*HH + 128*ke + 64*half + sj));
                    *(uint4*)&hst0[ke][sb][64*half + sj] = hv;
                    __syncwarp();
#pragma unroll
                    for (int ktl = 0; ktl < 4; ktl++) {
                        uint32_t addr = hb0 + (64*half + 16*ktl) * 2;
                        uint32_t bf[2];
                        bf[0] = bval ? lds_u32(addr)      : 0u;
                        bf[1] = bval ? lds_u32(addr + 16) : 0u;
                        mma16816(acc0,     A0[0][4*half + ktl], bf, acc0);
                        mma16816(acc0 + 4, A0[1][4*half + ktl], bf, acc0 + 4);
                        mma16816(acc1,     Ai[0][4*half + ktl], bf, acc1);
                        mma16816(acc1 + 4, Ai[1][4*half + ktl], bf, acc1 + 4);
                    }
                }
                // --- h1 chunk: feeds W_hh1 (acc1) ---
                {
                    const int* cp = &g_cnt1[s-1][ch][0];
                    int v; do { v = ld_acq(cp); } while (v < CNT_TARGET);
                    uint4 hv = __ldcg((const uint4*)(h1src + sb*HH + 128*ke + 64*half + sj));
                    *(uint4*)&hst1[ke][sb][64*half + sj] = hv;
                    __syncwarp();
#pragma unroll
                    for (int ktl = 0; ktl < 4; ktl++) {
                        uint32_t addr = hb1 + (64*half + 16*ktl) * 2;
                        uint32_t bf[2];
                        bf[0] = bval ? lds_u32(addr)      : 0u;
                        bf[1] = bval ? lds_u32(addr + 16) : 0u;
                        mma16816(acc1,     A1[0][4*half + ktl], bf, acc1);
                        mma16816(acc1 + 4, A1[1][4*half + ktl], bf, acc1 + 4);
                    }
                }
            }
            if (s >= 2 && bk < NCHUNK && tid == 32) {
                g_cnt0[s-2][bk][0] = 0;
                g_cnt1[s-2][bk][0] = 0;
            }
        }

        // store partials (acc cols n = (lane&3)*2 + {0,1}; n<4 lanes valid)
        if ((lane & 3) < 2) {
            int r0 = lane >> 2, bc = (lane & 3) * 2;
#pragma unroll
            for (int mt = 0; mt < 2; mt++) {
                *(float2*)&part0[ke*128 + (mt*16 + r0    )*4 + bc] = make_float2(acc0[mt*4+0], acc0[mt*4+1]);
                *(float2*)&part0[ke*128 + (mt*16 + r0 + 8)*4 + bc] = make_float2(acc0[mt*4+2], acc0[mt*4+3]);
                *(float2*)&part1[ke*128 + (mt*16 + r0    )*4 + bc] = make_float2(acc1[mt*4+0], acc1[mt*4+1]);
                *(float2*)&part1[ke*128 + (mt*16 + r0 + 8)*4 + bc] = make_float2(acc1[mt*4+2], acc1[mt*4+3]);
            }
        }
        __syncthreads();                     // the ONLY CTA-wide sync per wave

        if (tid < 32 && s < TT) {
            // warp0: layer0 tail -> h0[s]
            int cc = tid >> 2, b = tid & 3;
            float g4[4];
#pragma unroll
            for (int g = 0; g < 4; g++) {
                int rr = g*8 + cc;
                float sum = sxg[s & 1][rr*4 + b];
#pragma unroll
                for (int k8 = 0; k8 < 8; k8++) sum += part0[k8*128 + rr*4 + b];
                g4[g] = sum;
            }
            float iv = sigapx(g4[0]), fv = sigapx(g4[1]);
            float gv = tanhapx(g4[2]), ov = sigapx(g4[3]);
            float c = fv * csm0[tid] + iv * gv;
            csm0[tid] = c;
            float h = ov * tanhapx(c);
            g_h0buf[((s + 1) & 1) * BB * HH + b * HH + c0 + cc] = __float2bfloat16(h);
            red_rel_add(&g_cnt0[s][bk >> 3][0]);
        } else if (tid >= 32 && tid < 64) {
            // warp1: layer1 tail -> h1[s-1]
            int cc = lane >> 2, b = lane & 3;
            if (s > 0) {
                float g4[4];
#pragma unroll
                for (int g = 0; g < 4; g++) {
                    int rr = g*8 + cc;
                    float sum = b1v[g];
#pragma unroll
                    for (int k8 = 0; k8 < 8; k8++) sum += part1[k8*128 + rr*4 + b];
                    g4[g] = sum;
                }
                float iv = sigapx(g4[0]), fv = sigapx(g4[1]);
                float gv = tanhapx(g4[2]), ov = sigapx(g4[3]);
                float c = fv * csm1[lane] + iv * gv;
                csm1[lane] = c;
                float h = ov * tanhapx(c);
                __nv_bfloat16 hb = __float2bfloat16(h);
                g_h1buf[((s + 1) & 1) * BB * HH + b * HH + c0 + cc] = hb;
                if (s < TT) red_rel_add(&g_cnt1[s][bk >> 3][0]);
                hseq1[(size_t)(b*TT + (s-1)) * HH + c0 + cc] = hb;
            } else {
                // s==0: publish h1[-1] = 0 (overwrite replay-stale buffer)
                g_h1buf[1 * BB * HH + b * HH + c0 + cc] = __float2bfloat16(0.f);
                red_rel_add(&g_cnt1[0][bk >> 3][0]);
            }
        }
        // single-sync safety: no warp can write part*/hst* for wave s+1 before
        // its s polls succeed, which gate on warp0/warp1 releases of wave s;
        // sxg is double-buffered.
    }
}

// ---------------- log-softmax tail ---------------------------------------------
__global__ void rowlog_k(const float* __restrict__ ps) {
    int row  = blockIdx.x * 8 + (threadIdx.x >> 5);
    int lane = threadIdx.x & 31;
    const float* p = ps + (size_t)row * PSPITCH;
    float s = 0.f;
    for (int i = lane; i < PSPITCH; i += 32) s += p[i];   // pad entry is 0
#pragma unroll
    for (int m = 16; m > 0; m >>= 1) s += __shfl_xor_sync(0xffffffffu, s, m);
    if (lane == 0) g_rowoff[row] = logf(s);
}

__global__ void logsm_apply_k(float* __restrict__ C) {
    const int row = blockIdx.y;
    const int i = blockIdx.x * blockDim.x + threadIdx.x;
    if (i >= VV/4) return;
    float4* p = (float4*)(C + (size_t)row * VV);
    float off = __ldg(&g_rowoff[row]);
    float4 v = p[i];
    v.x -= off; v.y -= off; v.z -= off; v.w -= off;
    p[i] = v;
}

// ---------------- launcher ----------------------------------------------------
extern "C" void kernel_launch(void* const* d_in, const int* in_sizes, int n_in,
                              void* d_out, int out_size) {
    const int*   token_idx = (const int*)  d_in[0];
    const float* X     = (const float*)d_in[1];
    const float* W_ih0 = (const float*)d_in[2];
    const float* W_hh0 = (const float*)d_in[3];
    const float* b0    = (const float*)d_in[4];
    const float* W_ih1 = (const float*)d_in[5];
    const float* W_hh1 = (const float*)d_in[6];
    const float* b1    = (const float*)d_in[7];
    const float* W_out = (const float*)d_in[8];
    const float* b_out = (const float*)d_in[9];
    float* out = (float*)d_out;

    cudaFuncSetAttribute(gemm_bf16_k,
                         cudaFuncAttributeMaxDynamicSharedMemorySize,
                         GEMM_SMEM);

    void *p_emb, *p_Wih0, *p_Wout, *p_xg, *p_h1, *p_ps;
    cudaGetSymbolAddress(&p_emb,  g_emb);
    cudaGetSymbolAddress(&p_Wih0, g_Wih0);
    cudaGetSymbolAddress(&p_Wout, g_Wout);
    cudaGetSymbolAddress(&p_xg,   g_xg);
    cudaGetSymbolAddress(&p_h1,   g_h1);
    cudaGetSymbolAddress(&p_ps,   g_psum);

    // layer-0 input GEMM inputs
    gather_embed_k<<<(MROWS*(DD/4) + 255)/256, 256>>>(token_idx, X);
    f32_to_bf16_k<<<(G4H*DD/4 + 255)/256, 256>>>(W_ih0, (__nv_bfloat16*)p_Wih0, G4H*DD/4);
    // big W_out conversion (independent of everything else)
    f32_to_bf16_k<<<(VV*HH/4 + 255)/256, 256>>>(W_out, (__nv_bfloat16*)p_Wout, VV*HH/4);

    gemm_bf16_k<<<dim3(MROWS/128, G4H/128), 256, GEMM_SMEM>>>(
        (const __nv_bfloat16*)p_emb, (const __nv_bfloat16*)p_Wih0, b0,
        (float*)p_xg, MROWS, G4H, DD, (float*)p_ps, 0);

    // fused 2-layer recurrence (layer-1 input GEMM folded in)
    lstm_fused_k<<<NB_REC, 256>>>(
        (const float*)p_xg, W_hh0, W_ih1, b1, W_hh1, (__nv_bfloat16*)p_h1);

    // output projection (+ fused exp-row-sum partials) + log-softmax
    gemm_bf16_k<<<dim3(MROWS/128, NTILE), 256, GEMM_SMEM>>>(
        (const __nv_bfloat16*)p_h1, (const __nv_bfloat16*)p_Wout, b_out,
        out, MROWS, VV, HH, (float*)p_ps, 1);
    rowlog_k<<<MROWS/8, 256>>>((const float*)p_ps);
    logsm_apply_k<<<dim3((VV/4 + 255)/256, MROWS), 256>>>(out);
}

// round 12
// speedup vs baseline: 1.6328x; 1.6328x over previous
#include <cuda_runtime.h>
#include <cuda_bf16.h>
#include <cstdint>
#include <math.h>

// Problem constants
#define BB 4
#define TT 512
#define DD 512
#define HH 1024
#define VV 50000
#define VPAD 50048             // VV rounded up to 128
#define NTILE (VPAD/128)       // 391 n-tiles in the V GEMM
#define PSPITCH 392            // partial-sum row pitch
#define MROWS (BB*TT)          // 2048
#define G4H (4*HH)             // 4096
#define NB_REC 128             // recurrence CTAs (all resident wave-1)
#define NCHUNK 16              // h broadcast chunks per step (64 cols each)
#define CPC 8                  // CTAs per chunk
#define CNT_TARGET (CPC*32)    // 8 CTAs x 32 lanes release per chunk
#define HSP 136                // hstage bf16 row pitch (bank-conflict-light)

// ---------------- device scratch (static; zero-initialized) ------------------
__device__ __align__(256) __nv_bfloat16 g_emb [MROWS*DD];
__device__ __align__(256) __nv_bfloat16 g_Wih0[G4H*DD];
__device__ __align__(256) __nv_bfloat16 g_Wout[(size_t)VPAD*HH];  // tail rows stay 0
__device__ __align__(256) float         g_xg  [MROWS*G4H];
__device__ __align__(256) __nv_bfloat16 g_h1  [MROWS*HH];
__device__ __align__(256) __nv_bfloat16 g_h0buf[2*BB*HH];         // bf16 h0 exchange
__device__ __align__(256) __nv_bfloat16 g_h1buf[2*BB*HH];         // bf16 h1 exchange
__device__ __align__(256) int           g_cnt0[TT][NCHUNK][32];   // counter @[..][0]
__device__ __align__(256) int           g_cnt1[TT][NCHUNK][32];
__device__ __align__(256) float         g_psum[(size_t)MROWS*PSPITCH];
__device__ __align__(256) float         g_rowoff[MROWS];

// ---------------- small helpers ----------------------------------------------
__device__ __forceinline__ uint32_t smem_u32(const void* p) {
    return (uint32_t)__cvta_generic_to_shared(p);
}
__device__ __forceinline__ void ldmatrix_x4(uint32_t r[4], uint32_t addr) {
    asm volatile("ldmatrix.sync.aligned.m8n8.x4.shared.b16 {%0,%1,%2,%3}, [%4];"
                 : "=r"(r[0]), "=r"(r[1]), "=r"(r[2]), "=r"(r[3]) : "r"(addr));
}
__device__ __forceinline__ void ldmatrix_x2(uint32_t r[2], uint32_t addr) {
    asm volatile("ldmatrix.sync.aligned.m8n8.x2.shared.b16 {%0,%1}, [%2];"
                 : "=r"(r[0]), "=r"(r[1]) : "r"(addr));
}
__device__ __forceinline__ void mma16816(float d[4], const uint32_t a[4],
                                         const uint32_t b[2], const float c[4]) {
    asm volatile(
        "mma.sync.aligned.m16n8k16.row.col.f32.bf16.bf16.f32 "
        "{%0,%1,%2,%3}, {%4,%5,%6,%7}, {%8,%9}, {%10,%11,%12,%13};"
        : "=f"(d[0]), "=f"(d[1]), "=f"(d[2]), "=f"(d[3])
        : "r"(a[0]), "r"(a[1]), "r"(a[2]), "r"(a[3]),
          "r"(b[0]), "r"(b[1]),
          "f"(c[0]), "f"(c[1]), "f"(c[2]), "f"(c[3]));
}
__device__ __forceinline__ void cp_async16(uint32_t saddr, const void* g) {
    asm volatile("cp.async.cg.shared.global [%0], [%1], 16;" :: "r"(saddr), "l"(g));
}
__device__ __forceinline__ void cp_commit() {
    asm volatile("cp.async.commit_group;");
}
__device__ __forceinline__ int ld_acq(const int* p) {
    int v;
    asm volatile("ld.acquire.gpu.global.b32 %0, [%1];" : "=r"(v) : "l"(p) : "memory");
    return v;
}
__device__ __forceinline__ void red_rel_add(int* p) {
    int one = 1;
    asm volatile("red.release.gpu.global.add.s32 [%0], %1;" :: "l"(p), "r"(one) : "memory");
}
__device__ __forceinline__ float tanhapx(float x) {
    float y; asm("tanh.approx.f32 %0, %1;" : "=f"(y) : "f"(x)); return y;
}
__device__ __forceinline__ float sigapx(float x) {
    return fmaf(0.5f, tanhapx(0.5f * x), 0.5f);
}
__device__ __forceinline__ uint32_t pack_bf2(float x, float y) {
    __nv_bfloat162 b = __floats2bfloat162_rn(x, y);   // .x in low half
    return *(uint32_t*)&b;
}
__device__ __forceinline__ uint32_t lds_u32(uint32_t addr) {
    uint32_t v;
    asm volatile("ld.shared.b32 %0, [%1];" : "=r"(v) : "r"(addr));
    return v;
}

// ---------------- conversion / gather kernels ---------------------------------
__global__ void f32_to_bf16_k(const float* __restrict__ in,
                              __nv_bfloat16* __restrict__ out, int n4) {
    int i = blockIdx.x * blockDim.x + threadIdx.x;
    if (i >= n4) return;
    float4 v = *((const float4*)in + i);
    __nv_bfloat162 lo = __floats2bfloat162_rn(v.x, v.y);
    __nv_bfloat162 hi = __floats2bfloat162_rn(v.z, v.w);
    uint2 u;
    u.x = *(uint32_t*)&lo; u.y = *(uint32_t*)&hi;
    *((uint2*)out + i) = u;
}

__global__ void gather_embed_k(const int* __restrict__ idx,
                               const float* __restrict__ X) {
    int i = blockIdx.x * blockDim.x + threadIdx.x;   // one float4 each
    if (i >= MROWS * (DD/4)) return;
    int r = i >> 7;             // DD/4 = 128
    int j = i & 127;
    int tok = __ldg(&idx[r]);
    float4 v = *(const float4*)(X + (size_t)tok * DD + j * 4);
    __nv_bfloat162 lo = __floats2bfloat162_rn(v.x, v.y);
    __nv_bfloat162 hi = __floats2bfloat162_rn(v.z, v.w);
    uint2 u; u.x = *(uint32_t*)&lo; u.y = *(uint32_t*)&hi;
    *((uint2*)(g_emb + (size_t)r * DD) + j) = u;
}

// ---------------- bf16 MMA GEMM: C[M,N] = A[M,K] * B[N,K]^T + bias ------------
// CTA tile 128x128, K-tile 64, cp.async 2-stage pipeline, 8 warps (2Mx4N).
// (R9 configuration — best measured.)
#define GPITCH 72
#define GSTAGE (128*GPITCH)
#define GEMM_SMEM (4*GSTAGE*2)      // bytes

__global__ __launch_bounds__(256) void gemm_bf16_k(
    const __nv_bfloat16* __restrict__ A, const __nv_bfloat16* __restrict__ B,
    const float* __restrict__ bias, float* __restrict__ C,
    int M, int N, int K, float* __restrict__ psum, int do_sum)
{
    extern __shared__ __nv_bfloat16 gsm_[];
    __nv_bfloat16* sA = gsm_;                // [2][128][GPITCH]
    __nv_bfloat16* sB = gsm_ + 2*GSTAGE;     // [2][128][GPITCH]

    const int tid  = threadIdx.x;
    const int warp = tid >> 5, lane = tid & 31;
    const int wm = warp & 1, wn = warp >> 1;
    const int m0 = blockIdx.x * 128, n0 = blockIdx.y * 128;

    float acc[4][4][4];
#pragma unroll
    for (int a = 0; a < 4; a++)
#pragma unroll
        for (int b = 0; b < 4; b++)
#pragma unroll
            for (int c = 0; c < 4; c++) acc[a][b][c] = 0.f;

    const int ktiles = K >> 6;

    auto load_stage = [&](int st, int k0) {
#pragma unroll
        for (int i = 0; i < 4; i++) {
            int c   = tid + i * 256;
            int row = c >> 3;
            int col = (c & 7) << 3;
            uint32_t da = smem_u32(sA + st*GSTAGE + row*GPITCH + col);
            cp_async16(da, A + (size_t)(m0 + row) * K + k0 + col);
            uint32_t db = smem_u32(sB + st*GSTAGE + row*GPITCH + col);
            cp_async16(db, B + (size_t)(n0 + row) * K + k0 + col);
        }
    };

    load_stage(0, 0);
    cp_commit();

    for (int kt = 0; kt < ktiles; kt++) {
        if (kt + 1 < ktiles) {
            load_stage((kt + 1) & 1, (kt + 1) << 6);
            cp_commit();
            asm volatile("cp.async.wait_group 1;");
        } else {
            asm volatile("cp.async.wait_group 0;");
        }
        __syncthreads();

        const __nv_bfloat16* cA = sA + (kt & 1) * GSTAGE;
        const __nv_bfloat16* cB = sB + (kt & 1) * GSTAGE;
#pragma unroll
        for (int ks = 0; ks < 4; ks++) {
            uint32_t af[4][4], bf[4][2];
#pragma unroll
            for (int mt = 0; mt < 4; mt++) {
                uint32_t addr = smem_u32(
                    cA + (wm*64 + mt*16 + (lane & 15))*GPITCH
                       + ks*16 + ((lane >> 4) << 3));
                ldmatrix_x4(af[mt], addr);
            }
#pragma unroll
            for (int nt = 0; nt < 4; nt++) {
                uint32_t addr = smem_u32(
                    cB + (wn*32 + nt*8 + (lane & 7))*GPITCH
                       + ks*16 + (((lane >> 3) & 1) << 3));
                ldmatrix_x2(bf[nt], addr);
            }
#pragma unroll
            for (int mt = 0; mt < 4; mt++)
#pragma unroll
                for (int nt = 0; nt < 4; nt++)
                    mma16816(acc[mt][nt], af[mt], bf[nt], acc[mt][nt]);
        }
        __syncthreads();
    }

    // epilogue: write C (+ optional exp-row-sum partials)
    float rs[4][2];
#pragma unroll
    for (int mt = 0; mt < 4; mt++) { rs[mt][0] = 0.f; rs[mt][1] = 0.f; }

#pragma unroll
    for (int mt = 0; mt < 4; mt++)
#pragma unroll
        for (int nt = 0; nt < 4; nt++)
#pragma unroll
            for (int i = 0; i < 4; i++) {
                int row = m0 + wm*64 + mt*16 + (lane >> 2) + ((i >> 1) << 3);
                int col = n0 + wn*32 + nt*8 + ((lane & 3) << 1) + (i & 1);
                if (col < N) {
                    float v = acc[mt][nt][i] + __ldg(&bias[col]);
                    C[(size_t)row * N + col] = v;
                    if (do_sum) rs[mt][i >> 1] += __expf(v);
                }
            }

    if (do_sum) {
        float* ps = (float*)gsm_;            // [4][128] floats, reuse smem
#pragma unroll
        for (int mt = 0; mt < 4; mt++)
#pragma unroll
            for (int ih = 0; ih < 2; ih++) {
                float s = rs[mt][ih];
                s += __shfl_xor_sync(0xffffffffu, s, 1);
                s += __shfl_xor_sync(0xffffffffu, s, 2);
                if ((lane & 3) == 0) {
                    int rloc = wm*64 + mt*16 + (lane >> 2) + ih*8;
                    ps[wn*128 + rloc] = s;
                }
            }
        __syncthreads();
        if (tid < 128) {
            float s = ps[tid] + ps[128 + tid] + ps[256 + tid] + ps[384 + tid];
            psum[(size_t)(m0 + tid) * PSPITCH + blockIdx.y] = s;
        }
    }
}

// ---------------- fused 2-layer persistent LSTM -------------------------------
// 128 CTAs x 256 threads, TT+1 pipelined waves. Wave s computes layer0 step s
// (if s<TT) and layer1 step s-1 (if s>=1). Per wave, each warp does ONE
// combined poll of its 4 chunk counters (lane-groups poll concurrently,
// ballot-join) and then issues all 4 h-chunk loads back-to-back (MLP=4),
// collapsing 4 serial L2 round trips into ~1.
__global__ __launch_bounds__(256) void lstm_fused_k(
    const float* __restrict__ xg,
    const float* __restrict__ Whh0,
    const float* __restrict__ Wih1,
    const float* __restrict__ b1,
    const float* __restrict__ Whh1,
    __nv_bfloat16* __restrict__ hseq1)
{
    __shared__ __align__(16) __nv_bfloat16 hst0[8][4][HSP];  // staged h0 per warp
    __shared__ __align__(16) __nv_bfloat16 hst1[8][4][HSP];  // staged h1 per warp
    __shared__ __align__(16) float part0[8*128];
    __shared__ __align__(16) float part1[8*128];
    __shared__ float sxg[2][128];
    __shared__ float csm0[32], csm1[32];

    const int tid  = threadIdx.x;
    const int bk   = blockIdx.x;
    const int c0   = bk * 8;
    const int ke   = tid >> 5;
    const int lane = tid & 31;

    // clear counter slots a previous replay left set
    if (bk < NCHUNK && tid == 0) {
        g_cnt0[TT-2][bk][0] = 0; g_cnt0[TT-1][bk][0] = 0;
        g_cnt1[TT-2][bk][0] = 0; g_cnt1[TT-1][bk][0] = 0;
    }

    // ---- preload 3 weight sets as m16n8k16 A-fragments (fp32 -> bf16) ----
    uint32_t A0[2][8][4], Ai[2][8][4], A1[2][8][4];
    {
        const int r0 = lane >> 2;
        const int kc = (lane & 3) * 2;
#pragma unroll
        for (int mt = 0; mt < 2; mt++) {
#pragma unroll
            for (int kt = 0; kt < 8; kt++) {
                int kg = 128*ke + 16*kt + kc;
                int lrA = 16*mt + r0, lrB = lrA + 8;
                size_t oA = (size_t)((lrA >> 3)*HH + c0 + (lrA & 7)) * HH + kg;
                size_t oB = (size_t)((lrB >> 3)*HH + c0 + (lrB & 7)) * HH + kg;
#define LOADFRAG(W, F) { \
                float2 a0 = __ldg((const float2*)(W + oA)); \
                float2 a1 = __ldg((const float2*)(W + oB)); \
                float2 a2 = __ldg((const float2*)(W + oA + 8)); \
                float2 a3 = __ldg((const float2*)(W + oB + 8)); \
                F[mt][kt][0] = pack_bf2(a0.x, a0.y); \
                F[mt][kt][1] = pack_bf2(a1.x, a1.y); \
                F[mt][kt][2] = pack_bf2(a2.x, a2.y); \
                F[mt][kt][3] = pack_bf2(a3.x, a3.y); }
                LOADFRAG(Whh0, A0)
                LOADFRAG(Wih1, Ai)
                LOADFRAG(Whh1, A1)
#undef LOADFRAG
            }
        }
    }
    if (tid < 32) { csm0[tid] = 0.f; csm1[tid] = 0.f; }

    // warp1 tail: bias b1 for its 4 gates (cell cc = lane>>2)
    float b1v[4];
    {
        int cc = lane >> 2;
#pragma unroll
        for (int g = 0; g < 4; g++) b1v[g] = __ldg(&b1[g*HH + c0 + cc]);
    }

    // xg loader mapping (tid < 128): lr = tid>>2, b = tid&3
    const int lrx = tid >> 2, bx = tid & 3;
    const float* xgp = xg + (size_t)bx*TT*G4H + (lrx >> 3)*HH + c0 + (lrx & 7);

    // B-fragment read setup: n = lane>>2 (batch; >=4 -> zero)
    const int  bsel = (lane >> 2) & 3;
    const bool bval = lane < 16;
    const uint32_t hb0 = smem_u32(&hst0[ke][bsel][0]) + (lane & 3) * 4;
    const uint32_t hb1 = smem_u32(&hst1[ke][bsel][0]) + (lane & 3) * 4;
    const int sb = lane >> 3, sj = (lane & 7) * 8;   // stage store mapping

    // combined-poll mapping: lane-group grp = lane>>3 polls one of 4 counters
    const int grp = lane >> 3;
    const int chp = 2*ke + (grp & 1);

    __syncthreads();

    for (int s = 0; s <= TT; s++) {
        if (tid < 128 && s < TT) sxg[s & 1][tid] = __ldg(xgp + (size_t)s * G4H);

        float acc0[8] = {0,0,0,0,0,0,0,0};   // layer0 gates (2 m-tiles x 4)
        float acc1[8] = {0,0,0,0,0,0,0,0};   // layer1 gates

        if (s > 0) {
            const __nv_bfloat16* h0src = g_h0buf + (s & 1) * BB * HH;
            const __nv_bfloat16* h1src = g_h1buf + (s & 1) * BB * HH;

            // ---- ONE combined poll of all 4 chunk counters ----
            {
                const int* cp = (grp < 2) ? &g_cnt0[s-1][chp][0]
                                          : &g_cnt1[s-1][chp][0];
                int ok;
                do { ok = (ld_acq(cp) >= CNT_TARGET); }
                while (__ballot_sync(0xffffffffu, ok) != 0xffffffffu);
            }

            // ---- stage all 4 chunks back-to-back (MLP = 4) ----
            uint4 v00 = __ldcg((const uint4*)(h0src + sb*HH + 128*ke +      sj));
            uint4 v01 = __ldcg((const uint4*)(h0src + sb*HH + 128*ke + 64 + sj));
            uint4 v10 = __ldcg((const uint4*)(h1src + sb*HH + 128*ke +      sj));
            uint4 v11 = __ldcg((const uint4*)(h1src + sb*HH + 128*ke + 64 + sj));
            *(uint4*)&hst0[ke][sb][     sj] = v00;
            *(uint4*)&hst0[ke][sb][64 + sj] = v01;
            *(uint4*)&hst1[ke][sb][     sj] = v10;
            *(uint4*)&hst1[ke][sb][64 + sj] = v11;
            __syncwarp();

            // ---- MMAs: h0 feeds acc0 (W_hh0) + acc1 (W_ih1); h1 feeds acc1 ----
#pragma unroll
            for (int kq = 0; kq < 8; kq++) {          // 8 k-tiles of 16
                uint32_t addr = hb0 + (16*kq) * 2;
                uint32_t bf[2];
                bf[0] = bval ? lds_u32(addr)      : 0u;
                bf[1] = bval ? lds_u32(addr + 16) : 0u;
                mma16816(acc0,     A0[0][kq], bf, acc0);
                mma16816(acc0 + 4, A0[1][kq], bf, acc0 + 4);
                mma16816(acc1,     Ai[0][kq], bf, acc1);
                mma16816(acc1 + 4, Ai[1][kq], bf, acc1 + 4);
            }
#pragma unroll
            for (int kq = 0; kq < 8; kq++) {
                uint32_t addr = hb1 + (16*kq) * 2;
                uint32_t bf[2];
                bf[0] = bval ? lds_u32(addr)      : 0u;
                bf[1] = bval ? lds_u32(addr + 16) : 0u;
                mma16816(acc1,     A1[0][kq], bf, acc1);
                mma16816(acc1 + 4, A1[1][kq], bf, acc1 + 4);
            }

            if (s >= 2 && bk < NCHUNK && tid == 32) {
                g_cnt0[s-2][bk][0] = 0;
                g_cnt1[s-2][bk][0] = 0;
            }
        }

        // store partials (acc cols n = (lane&3)*2 + {0,1}; n<4 lanes valid)
        if ((lane & 3) < 2) {
            int r0 = lane >> 2, bc = (lane & 3) * 2;
#pragma unroll
            for (int mt = 0; mt < 2; mt++) {
                *(float2*)&part0[ke*128 + (mt*16 + r0    )*4 + bc] = make_float2(acc0[mt*4+0], acc0[mt*4+1]);
                *(float2*)&part0[ke*128 + (mt*16 + r0 + 8)*4 + bc] = make_float2(acc0[mt*4+2], acc0[mt*4+3]);
                *(float2*)&part1[ke*128 + (mt*16 + r0    )*4 + bc] = make_float2(acc1[mt*4+0], acc1[mt*4+1]);
                *(float2*)&part1[ke*128 + (mt*16 + r0 + 8)*4 + bc] = make_float2(acc1[mt*4+2], acc1[mt*4+3]);
            }
        }
        __syncthreads();                     // the ONLY CTA-wide sync per wave

        if (tid < 32 && s < TT) {
            // warp0: layer0 tail -> h0[s]
            int cc = tid >> 2, b = tid & 3;
            float g4[4];
#pragma unroll
            for (int g = 0; g < 4; g++) {
                int rr = g*8 + cc;
                float sum = sxg[s & 1][rr*4 + b];
#pragma unroll
                for (int k8 = 0; k8 < 8; k8++) sum += part0[k8*128 + rr*4 + b];
                g4[g] = sum;
            }
            float iv = sigapx(g4[0]), fv = sigapx(g4[1]);
            float gv = tanhapx(g4[2]), ov = sigapx(g4[3]);
            float c = fv * csm0[tid] + iv * gv;
            csm0[tid] = c;
            float h = ov * tanhapx(c);
            g_h0buf[((s + 1) & 1) * BB * HH + b * HH + c0 + cc] = __float2bfloat16(h);
            red_rel_add(&g_cnt0[s][bk >> 3][0]);
        } else if (tid >= 32 && tid < 64) {
            // warp1: layer1 tail -> h1[s-1]
            int cc = lane >> 2, b = lane & 3;
            if (s > 0) {
                float g4[4];
#pragma unroll
                for (int g = 0; g < 4; g++) {
                    int rr = g*8 + cc;
                    float sum = b1v[g];
#pragma unroll
                    for (int k8 = 0; k8 < 8; k8++) sum += part1[k8*128 + rr*4 + b];
                    g4[g] = sum;
                }
                float iv = sigapx(g4[0]), fv = sigapx(g4[1]);
                float gv = tanhapx(g4[2]), ov = sigapx(g4[3]);
                float c = fv * csm1[lane] + iv * gv;
                csm1[lane] = c;
                float h = ov * tanhapx(c);
                __nv_bfloat16 hb = __float2bfloat16(h);
                g_h1buf[((s + 1) & 1) * BB * HH + b * HH + c0 + cc] = hb;
                if (s < TT) red_rel_add(&g_cnt1[s][bk >> 3][0]);
                hseq1[(size_t)(b*TT + (s-1)) * HH + c0 + cc] = hb;
            } else {
                // s==0: publish h1[-1] = 0 (overwrite replay-stale buffer)
                g_h1buf[1 * BB * HH + b * HH + c0 + cc] = __float2bfloat16(0.f);
                red_rel_add(&g_cnt1[0][bk >> 3][0]);
            }
        }
        // single-sync safety: no warp can write part*/hst* for wave s+1 before
        // its s polls succeed, which gate on warp0/warp1 releases of wave s;
        // sxg is double-buffered.
    }
}

// ---------------- log-softmax tail ---------------------------------------------
__global__ void rowlog_k(const float* __restrict__ ps) {
    int row  = blockIdx.x * 8 + (threadIdx.x >> 5);
    int lane = threadIdx.x & 31;
    const float* p = ps + (size_t)row * PSPITCH;
    float s = 0.f;
    for (int i = lane; i < PSPITCH; i += 32) s += p[i];   // pad entry is 0
#pragma unroll
    for (int m = 16; m > 0; m >>= 1) s += __shfl_xor_sync(0xffffffffu, s, m);
    if (lane == 0) g_rowoff[row] = logf(s);
}

__global__ void logsm_apply_k(float* __restrict__ C) {
    const int row = blockIdx.y;
    const int i = blockIdx.x * blockDim.x + threadIdx.x;
    if (i >= VV/4) return;
    float4* p = (float4*)(C + (size_t)row * VV);
    float off = __ldg(&g_rowoff[row]);
    float4 v = p[i];
    v.x -= off; v.y -= off; v.z -= off; v.w -= off;
    p[i] = v;
}

// ---------------- launcher ----------------------------------------------------
extern "C" void kernel_launch(void* const* d_in, const int* in_sizes, int n_in,
                              void* d_out, int out_size) {
    const int*   token_idx = (const int*)  d_in[0];
    const float* X     = (const float*)d_in[1];
    const float* W_ih0 = (const float*)d_in[2];
    const float* W_hh0 = (const float*)d_in[3];
    const float* b0    = (const float*)d_in[4];
    const float* W_ih1 = (const float*)d_in[5];
    const float* W_hh1 = (const float*)d_in[6];
    const float* b1    = (const float*)d_in[7];
    const float* W_out = (const float*)d_in[8];
    const float* b_out = (const float*)d_in[9];
    float* out = (float*)d_out;

    cudaFuncSetAttribute(gemm_bf16_k,
                         cudaFuncAttributeMaxDynamicSharedMemorySize,
                         GEMM_SMEM);

    void *p_emb, *p_Wih0, *p_Wout, *p_xg, *p_h1, *p_ps;
    cudaGetSymbolAddress(&p_emb,  g_emb);
    cudaGetSymbolAddress(&p_Wih0, g_Wih0);
    cudaGetSymbolAddress(&p_Wout, g_Wout);
    cudaGetSymbolAddress(&p_xg,   g_xg);
    cudaGetSymbolAddress(&p_h1,   g_h1);
    cudaGetSymbolAddress(&p_ps,   g_psum);

    // layer-0 input GEMM inputs
    gather_embed_k<<<(MROWS*(DD/4) + 255)/256, 256>>>(token_idx, X);
    f32_to_bf16_k<<<(G4H*DD/4 + 255)/256, 256>>>(W_ih0, (__nv_bfloat16*)p_Wih0, G4H*DD/4);
    // big W_out conversion (independent of everything else)
    f32_to_bf16_k<<<(VV*HH/4 + 255)/256, 256>>>(W_out, (__nv_bfloat16*)p_Wout, VV*HH/4);

    gemm_bf16_k<<<dim3(MROWS/128, G4H/128), 256, GEMM_SMEM>>>(
        (const __nv_bfloat16*)p_emb, (const __nv_bfloat16*)p_Wih0, b0,
        (float*)p_xg, MROWS, G4H, DD, (float*)p_ps, 0);

    // fused 2-layer recurrence (layer-1 input GEMM folded in)
    lstm_fused_k<<<NB_REC, 256>>>(
        (const float*)p_xg, W_hh0, W_ih1, b1, W_hh1, (__nv_bfloat16*)p_h1);

    // output projection (+ fused exp-row-sum partials) + log-softmax
    gemm_bf16_k<<<dim3(MROWS/128, NTILE), 256, GEMM_SMEM>>>(
        (const __nv_bfloat16*)p_h1, (const __nv_bfloat16*)p_Wout, b_out,
        out, MROWS, VV, HH, (float*)p_ps, 1);
    rowlog_k<<<MROWS/8, 256>>>((const float*)p_ps);
    logsm_apply_k<<<dim3((VV/4 + 255)/256, MROWS), 256>>>(out);
}

// round 15
// speedup vs baseline: 1.6337x; 1.0005x over previous
#include <cuda_runtime.h>
#include <cuda_bf16.h>
#include <cstdint>
#include <math.h>

// Problem constants
#define BB 4
#define TT 512
#define DD 512
#define HH 1024
#define VV 50000
#define VPAD 50048             // VV rounded up to 128
#define NTILE (VPAD/128)       // 391 n-tiles in the V GEMM
#define PSPITCH 392            // partial-sum row pitch
#define MROWS (BB*TT)          // 2048
#define G4H (4*HH)             // 4096
#define NB_REC 128             // recurrence CTAs (all resident wave-1)
#define NCHUNK 16              // h broadcast chunks per step (64 cols each)
#define CPC 8                  // CTAs per chunk
#define CNT_TARGET (CPC*32)    // 8 CTAs x 32 lanes release per chunk
#define HSP 136                // hstage bf16 row pitch (bank-conflict-light)

// ---------------- device scratch (static; zero-initialized) ------------------
__device__ __align__(256) __nv_bfloat16 g_emb [MROWS*DD];
__device__ __align__(256) __nv_bfloat16 g_Wih0[G4H*DD];
__device__ __align__(256) __nv_bfloat16 g_Wout[(size_t)VPAD*HH];  // tail rows stay 0
__device__ __align__(256) float         g_xg  [MROWS*G4H];
__device__ __align__(256) __nv_bfloat16 g_h1  [MROWS*HH];
__device__ __align__(256) __nv_bfloat16 g_h0buf[2*BB*HH];         // bf16 h0 exchange
__device__ __align__(256) __nv_bfloat16 g_h1buf[2*BB*HH];         // bf16 h1 exchange
__device__ __align__(256) int           g_cnt0[TT][NCHUNK][32];   // counter @[..][0]
__device__ __align__(256) int           g_cnt1[TT][NCHUNK][32];
__device__ __align__(256) float         g_psum[(size_t)MROWS*PSPITCH];
__device__ __align__(256) float         g_rowoff[MROWS];

// ---------------- small helpers ----------------------------------------------
__device__ __forceinline__ uint32_t smem_u32(const void* p) {
    return (uint32_t)__cvta_generic_to_shared(p);
}
__device__ __forceinline__ void ldmatrix_x4(uint32_t r[4], uint32_t addr) {
    asm volatile("ldmatrix.sync.aligned.m8n8.x4.shared.b16 {%0,%1,%2,%3}, [%4];"
                 : "=r"(r[0]), "=r"(r[1]), "=r"(r[2]), "=r"(r[3]) : "r"(addr));
}
__device__ __forceinline__ void ldmatrix_x2(uint32_t r[2], uint32_t addr) {
    asm volatile("ldmatrix.sync.aligned.m8n8.x2.shared.b16 {%0,%1}, [%2];"
                 : "=r"(r[0]), "=r"(r[1]) : "r"(addr));
}
__device__ __forceinline__ void mma16816(float d[4], const uint32_t a[4],
                                         const uint32_t b[2], const float c[4]) {
    asm volatile(
        "mma.sync.aligned.m16n8k16.row.col.f32.bf16.bf16.f32 "
        "{%0,%1,%2,%3}, {%4,%5,%6,%7}, {%8,%9}, {%10,%11,%12,%13};"
        : "=f"(d[0]), "=f"(d[1]), "=f"(d[2]), "=f"(d[3])
        : "r"(a[0]), "r"(a[1]), "r"(a[2]), "r"(a[3]),
          "r"(b[0]), "r"(b[1]),
          "f"(c[0]), "f"(c[1]), "f"(c[2]), "f"(c[3]));
}
__device__ __forceinline__ void cp_async16(uint32_t saddr, const void* g) {
    asm volatile("cp.async.cg.shared.global [%0], [%1], 16;" :: "r"(saddr), "l"(g));
}
__device__ __forceinline__ void cp_commit() {
    asm volatile("cp.async.commit_group;");
}
__device__ __forceinline__ int ld_acq(const int* p) {
    int v;
    asm volatile("ld.acquire.gpu.global.b32 %0, [%1];" : "=r"(v) : "l"(p) : "memory");
    return v;
}
__device__ __forceinline__ void red_rel_add(int* p) {
    int one = 1;
    asm volatile("red.release.gpu.global.add.s32 [%0], %1;" :: "l"(p), "r"(one) : "memory");
}
__device__ __forceinline__ float tanhapx(float x) {
    float y; asm("tanh.approx.f32 %0, %1;" : "=f"(y) : "f"(x)); return y;
}
__device__ __forceinline__ float sigapx(float x) {
    return fmaf(0.5f, tanhapx(0.5f * x), 0.5f);
}
__device__ __forceinline__ uint32_t pack_bf2(float x, float y) {
    __nv_bfloat162 b = __floats2bfloat162_rn(x, y);   // .x in low half
    return *(uint32_t*)&b;
}
__device__ __forceinline__ uint32_t lds_u32(uint32_t addr) {
    uint32_t v;
    asm volatile("ld.shared.b32 %0, [%1];" : "=r"(v) : "r"(addr));
    return v;
}
// exp(x) for |x| << 1: degree-4 Taylor (pure FFMA, no MUFU)
__device__ __forceinline__ float pexp(float x) {
    float p = fmaf(x, 0.041666667f, 0.166666667f);
    p = fmaf(x, p, 0.5f);
    p = fmaf(x, p, 1.0f);
    return fmaf(x, p, 1.0f);
}

// ---------------- conversion / gather kernels ---------------------------------
__global__ void f32_to_bf16_k(const float* __restrict__ in,
                              __nv_bfloat16* __restrict__ out, int n4) {
    int i = blockIdx.x * blockDim.x + threadIdx.x;
    if (i >= n4) return;
    float4 v = *((const float4*)in + i);
    __nv_bfloat162 lo = __floats2bfloat162_rn(v.x, v.y);
    __nv_bfloat162 hi = __floats2bfloat162_rn(v.z, v.w);
    uint2 u;
    u.x = *(uint32_t*)&lo; u.y = *(uint32_t*)&hi;
    *((uint2*)out + i) = u;
}

__global__ void gather_embed_k(const int* __restrict__ idx,
                               const float* __restrict__ X) {
    int i = blockIdx.x * blockDim.x + threadIdx.x;   // one float4 each
    if (i >= MROWS * (DD/4)) return;
    int r = i >> 7;             // DD/4 = 128
    int j = i & 127;
    int tok = __ldg(&idx[r]);
    float4 v = *(const float4*)(X + (size_t)tok * DD + j * 4);
    __nv_bfloat162 lo = __floats2bfloat162_rn(v.x, v.y);
    __nv_bfloat162 hi = __floats2bfloat162_rn(v.z, v.w);
    uint2 u; u.x = *(uint32_t*)&lo; u.y = *(uint32_t*)&hi;
    *((uint2*)(g_emb + (size_t)r * DD) + j) = u;
}

// ---------------- bf16 MMA GEMM: C[M,N] = A[M,K] * B[N,K]^T + bias ------------
// CTA tile 128x128, K-tile 64, cp.async 3-stage pipeline (prefetch-before-wait,
// 2 tiles always in flight), 8 warps (2Mx4N, warp tile 64x32).
// do_sum: also emit per-tile poly-exp row-sums into psum[row*PSPITCH + by].
#define GPITCH 72
#define GSTAGE (128*GPITCH)
#define NSTG 3
#define GEMM_SMEM (NSTG*2*GSTAGE*2)      // bytes = 110592

__global__ __launch_bounds__(256) void gemm_bf16_k(
    const __nv_bfloat16* __restrict__ A, const __nv_bfloat16* __restrict__ B,
    const float* __restrict__ bias, float* __restrict__ C,
    int M, int N, int K, float* __restrict__ psum, int do_sum)
{
    extern __shared__ __nv_bfloat16 gsm_[];

    const int tid  = threadIdx.x;
    const int warp = tid >> 5, lane = tid & 31;
    const int wm = warp & 1, wn = warp >> 1;
    const int m0 = blockIdx.x * 128, n0 = blockIdx.y * 128;

    float acc[4][4][4];
#pragma unroll
    for (int a = 0; a < 4; a++)
#pragma unroll
        for (int b = 0; b < 4; b++)
#pragma unroll
            for (int c = 0; c < 4; c++) acc[a][b][c] = 0.f;

    const int ktiles = K >> 6;

    auto load_stage = [&](int st, int k0) {
        __nv_bfloat16* sA = gsm_ + st * 2 * GSTAGE;
        __nv_bfloat16* sB = sA + GSTAGE;
#pragma unroll
        for (int i = 0; i < 4; i++) {
            int c   = tid + i * 256;
            int row = c >> 3;
            int col = (c & 7) << 3;
            cp_async16(smem_u32(sA + row*GPITCH + col),
                       A + (size_t)(m0 + row) * K + k0 + col);
            cp_async16(smem_u32(sB + row*GPITCH + col),
                       B + (size_t)(n0 + row) * K + k0 + col);
        }
    };

    load_stage(0, 0);
    cp_commit();
    if (ktiles > 1) { load_stage(1, 64); cp_commit(); }

    for (int kt = 0; kt < ktiles; kt++) {
        // prefetch tile kt+2 into the slot freed by tile kt-1 (loads in flight
        // while we wait for tile kt)
        if (kt + 2 < ktiles) {
            int st2 = kt + 2; while (st2 >= NSTG) st2 -= NSTG;
            load_stage(st2, (kt + 2) << 6);
            cp_commit();
        }
        int rem = ktiles - 1 - kt;               // newer tiles allowed pending
        if (rem >= 2)      asm volatile("cp.async.wait_group 2;");
        else if (rem == 1) asm volatile("cp.async.wait_group 1;");
        else               asm volatile("cp.async.wait_group 0;");
        __syncthreads();

        int st = kt; while (st >= NSTG) st -= NSTG;
        const __nv_bfloat16* cA = gsm_ + st * 2 * GSTAGE;
        const __nv_bfloat16* cB = cA + GSTAGE;
#pragma unroll
        for (int ks = 0; ks < 4; ks++) {
            uint32_t af[4][4], bf[4][2];
#pragma unroll
            for (int mt = 0; mt < 4; mt++) {
                uint32_t addr = smem_u32(
                    cA + (wm*64 + mt*16 + (lane & 15))*GPITCH
                       + ks*16 + ((lane >> 4) << 3));
                ldmatrix_x4(af[mt], addr);
            }
#pragma unroll
            for (int nt = 0; nt < 4; nt++) {
                uint32_t addr = smem_u32(
                    cB + (wn*32 + nt*8 + (lane & 7))*GPITCH
                       + ks*16 + (((lane >> 3) & 1) << 3));
                ldmatrix_x2(bf[nt], addr);
            }
#pragma unroll
            for (int mt = 0; mt < 4; mt++)
#pragma unroll
                for (int nt = 0; nt < 4; nt++)
                    mma16816(acc[mt][nt], af[mt], bf[nt], acc[mt][nt]);
        }
        __syncthreads();
    }

    // epilogue: write C (+ optional poly-exp row-sum partials)
    float rs[4][2];
#pragma unroll
    for (int mt = 0; mt < 4; mt++) { rs[mt][0] = 0.f; rs[mt][1] = 0.f; }

#pragma unroll
    for (int mt = 0; mt < 4; mt++)
#pragma unroll
        for (int nt = 0; nt < 4; nt++)
#pragma unroll
            for (int i = 0; i < 4; i++) {
                int row = m0 + wm*64 + mt*16 + (lane >> 2) + ((i >> 1) << 3);
                int col = n0 + wn*32 + nt*8 + ((lane & 3) << 1) + (i & 1);
                if (col < N) {
                    float v = acc[mt][nt][i] + __ldg(&bias[col]);
                    C[(size_t)row * N + col] = v;
                    if (do_sum) rs[mt][i >> 1] += pexp(v);
                }
            }

    if (do_sum) {
        float* ps = (float*)gsm_;            // [4][128] floats, reuse smem
#pragma unroll
        for (int mt = 0; mt < 4; mt++)
#pragma unroll
            for (int ih = 0; ih < 2; ih++) {
                float s = rs[mt][ih];
                s += __shfl_xor_sync(0xffffffffu, s, 1);
                s += __shfl_xor_sync(0xffffffffu, s, 2);
                if ((lane & 3) == 0) {
                    int rloc = wm*64 + mt*16 + (lane >> 2) + ih*8;
                    ps[wn*128 + rloc] = s;
                }
            }
        __syncthreads();
        if (tid < 128) {
            float s = ps[tid] + ps[128 + tid] + ps[256 + tid] + ps[384 + tid];
            psum[(size_t)(m0 + tid) * PSPITCH + blockIdx.y] = s;
        }
    }
}

// ---------------- fused 2-layer persistent LSTM (R12; unchanged) ---------------
__global__ __launch_bounds__(256) void lstm_fused_k(
    const float* __restrict__ xg,
    const float* __restrict__ Whh0,
    const float* __restrict__ Wih1,
    const float* __restrict__ b1,
    const float* __restrict__ Whh1,
    __nv_bfloat16* __restrict__ hseq1)
{
    __shared__ __align__(16) __nv_bfloat16 hst0[8][4][HSP];
    __shared__ __align__(16) __nv_bfloat16 hst1[8][4][HSP];
    __shared__ __align__(16) float part0[8*128];
    __shared__ __align__(16) float part1[8*128];
    __shared__ float sxg[2][128];
    __shared__ float csm0[32], csm1[32];

    const int tid  = threadIdx.x;
    const int bk   = blockIdx.x;
    const int c0   = bk * 8;
    const int ke   = tid >> 5;
    const int lane = tid & 31;

    if (bk < NCHUNK && tid == 0) {
        g_cnt0[TT-2][bk][0] = 0; g_cnt0[TT-1][bk][0] = 0;
        g_cnt1[TT-2][bk][0] = 0; g_cnt1[TT-1][bk][0] = 0;
    }

    uint32_t A0[2][8][4], Ai[2][8][4], A1[2][8][4];
    {
        const int r0 = lane >> 2;
        const int kc = (lane & 3) * 2;
#pragma unroll
        for (int mt = 0; mt < 2; mt++) {
#pragma unroll
            for (int kt = 0; kt < 8; kt++) {
                int kg = 128*ke + 16*kt + kc;
                int lrA = 16*mt + r0, lrB = lrA + 8;
                size_t oA = (size_t)((lrA >> 3)*HH + c0 + (lrA & 7)) * HH + kg;
                size_t oB = (size_t)((lrB >> 3)*HH + c0 + (lrB & 7)) * HH + kg;
#define LOADFRAG(W, F) { \
                float2 a0 = __ldg((const float2*)(W + oA)); \
                float2 a1 = __ldg((const float2*)(W + oB)); \
                float2 a2 = __ldg((const float2*)(W + oA + 8)); \
                float2 a3 = __ldg((const float2*)(W + oB + 8)); \
                F[mt][kt][0] = pack_bf2(a0.x, a0.y); \
                F[mt][kt][1] = pack_bf2(a1.x, a1.y); \
                F[mt][kt][2] = pack_bf2(a2.x, a2.y); \
                F[mt][kt][3] = pack_bf2(a3.x, a3.y); }
                LOADFRAG(Whh0, A0)
                LOADFRAG(Wih1, Ai)
                LOADFRAG(Whh1, A1)
#undef LOADFRAG
            }
        }
    }
    if (tid < 32) { csm0[tid] = 0.f; csm1[tid] = 0.f; }

    float b1v[4];
    {
        int cc = lane >> 2;
#pragma unroll
        for (int g = 0; g < 4; g++) b1v[g] = __ldg(&b1[g*HH + c0 + cc]);
    }

    const int lrx = tid >> 2, bx = tid & 3;
    const float* xgp = xg + (size_t)bx*TT*G4H + (lrx >> 3)*HH + c0 + (lrx & 7);

    const int  bsel = (lane >> 2) & 3;
    const bool bval = lane < 16;
    const uint32_t hb0 = smem_u32(&hst0[ke][bsel][0]) + (lane & 3) * 4;
    const uint32_t hb1 = smem_u32(&hst1[ke][bsel][0]) + (lane & 3) * 4;
    const int sb = lane >> 3, sj = (lane & 7) * 8;

    const int grp = lane >> 3;
    const int chp = 2*ke + (grp & 1);

    __syncthreads();

    for (int s = 0; s <= TT; s++) {
        if (tid < 128 && s < TT) sxg[s & 1][tid] = __ldg(xgp + (size_t)s * G4H);

        float acc0[8] = {0,0,0,0,0,0,0,0};
        float acc1[8] = {0,0,0,0,0,0,0,0};

        if (s > 0) {
            const __nv_bfloat16* h0src = g_h0buf + (s & 1) * BB * HH;
            const __nv_bfloat16* h1src = g_h1buf + (s & 1) * BB * HH;

            {
                const int* cp = (grp < 2) ? &g_cnt0[s-1][chp][0]
                                          : &g_cnt1[s-1][chp][0];
                int ok;
                do { ok = (ld_acq(cp) >= CNT_TARGET); }
                while (__ballot_sync(0xffffffffu, ok) != 0xffffffffu);
            }

            uint4 v00 = __ldcg((const uint4*)(h0src + sb*HH + 128*ke +      sj));
            uint4 v01 = __ldcg((const uint4*)(h0src + sb*HH + 128*ke + 64 + sj));
            uint4 v10 = __ldcg((const uint4*)(h1src + sb*HH + 128*ke +      sj));
            uint4 v11 = __ldcg((const uint4*)(h1src + sb*HH + 128*ke + 64 + sj));
            *(uint4*)&hst0[ke][sb][     sj] = v00;
            *(uint4*)&hst0[ke][sb][64 + sj] = v01;
            *(uint4*)&hst1[ke][sb][     sj] = v10;
            *(uint4*)&hst1[ke][sb][64 + sj] = v11;
            __syncwarp();

#pragma unroll
            for (int kq = 0; kq < 8; kq++) {
                uint32_t addr = hb0 + (16*kq) * 2;
                uint32_t bf[2];
                bf[0] = bval ? lds_u32(addr)      : 0u;
                bf[1] = bval ? lds_u32(addr + 16) : 0u;
                mma16816(acc0,     A0[0][kq], bf, acc0);
                mma16816(acc0 + 4, A0[1][kq], bf, acc0 + 4);
                mma16816(acc1,     Ai[0][kq], bf, acc1);
                mma16816(acc1 + 4, Ai[1][kq], bf, acc1 + 4);
            }
#pragma unroll
            for (int kq = 0; kq < 8; kq++) {
                uint32_t addr = hb1 + (16*kq) * 2;
                uint32_t bf[2];
                bf[0] = bval ? lds_u32(addr)      : 0u;
                bf[1] = bval ? lds_u32(addr + 16) : 0u;
                mma16816(acc1,     A1[0][kq], bf, acc1);
                mma16816(acc1 + 4, A1[1][kq], bf, acc1 + 4);
            }

            if (s >= 2 && bk < NCHUNK && tid == 32) {
                g_cnt0[s-2][bk][0] = 0;
                g_cnt1[s-2][bk][0] = 0;
            }
        }

        if ((lane & 3) < 2) {
            int r0 = lane >> 2, bc = (lane & 3) * 2;
#pragma unroll
            for (int mt = 0; mt < 2; mt++) {
                *(float2*)&part0[ke*128 + (mt*16 + r0    )*4 + bc] = make_float2(acc0[mt*4+0], acc0[mt*4+1]);
                *(float2*)&part0[ke*128 + (mt*16 + r0 + 8)*4 + bc] = make_float2(acc0[mt*4+2], acc0[mt*4+3]);
                *(float2*)&part1[ke*128 + (mt*16 + r0    )*4 + bc] = make_float2(acc1[mt*4+0], acc1[mt*4+1]);
                *(float2*)&part1[ke*128 + (mt*16 + r0 + 8)*4 + bc] = make_float2(acc1[mt*4+2], acc1[mt*4+3]);
            }
        }
        __syncthreads();

        if (tid < 32 && s < TT) {
            int cc = tid >> 2, b = tid & 3;
            float g4[4];
#pragma unroll
            for (int g = 0; g < 4; g++) {
                int rr = g*8 + cc;
                float sum = sxg[s & 1][rr*4 + b];
#pragma unroll
                for (int k8 = 0; k8 < 8; k8++) sum += part0[k8*128 + rr*4 + b];
                g4[g] = sum;
            }
            float iv = sigapx(g4[0]), fv = sigapx(g4[1]);
            float gv = tanhapx(g4[2]), ov = sigapx(g4[3]);
            float c = fv * csm0[tid] + iv * gv;
            csm0[tid] = c;
            float h = ov * tanhapx(c);
            g_h0buf[((s + 1) & 1) * BB * HH + b * HH + c0 + cc] = __float2bfloat16(h);
            red_rel_add(&g_cnt0[s][bk >> 3][0]);
        } else if (tid >= 32 && tid < 64) {
            int cc = lane >> 2, b = lane & 3;
            if (s > 0) {
                float g4[4];
#pragma unroll
                for (int g = 0; g < 4; g++) {
                    int rr = g*8 + cc;
                    float sum = b1v[g];
#pragma unroll
                    for (int k8 = 0; k8 < 8; k8++) sum += part1[k8*128 + rr*4 + b];
                    g4[g] = sum;
                }
                float iv = sigapx(g4[0]), fv = sigapx(g4[1]);
                float gv = tanhapx(g4[2]), ov = sigapx(g4[3]);
                float c = fv * csm1[lane] + iv * gv;
                csm1[lane] = c;
                float h = ov * tanhapx(c);
                __nv_bfloat16 hb = __float2bfloat16(h);
                g_h1buf[((s + 1) & 1) * BB * HH + b * HH + c0 + cc] = hb;
                if (s < TT) red_rel_add(&g_cnt1[s][bk >> 3][0]);
                hseq1[(size_t)(b*TT + (s-1)) * HH + c0 + cc] = hb;
            } else {
                g_h1buf[1 * BB * HH + b * HH + c0 + cc] = __float2bfloat16(0.f);
                red_rel_add(&g_cnt1[0][bk >> 3][0]);
            }
        }
    }
}

// ---------------- log-softmax tail ---------------------------------------------
__global__ void rowlog_k(const float* __restrict__ ps) {
    int row  = blockIdx.x * 8 + (threadIdx.x >> 5);
    int lane = threadIdx.x & 31;
    const float* p = ps + (size_t)row * PSPITCH;
    float s = 0.f;
    for (int i = lane; i < PSPITCH; i += 32) s += p[i];   // pad entry is 0
#pragma unroll
    for (int m = 16; m > 0; m >>= 1) s += __shfl_xor_sync(0xffffffffu, s, m);
    if (lane == 0) g_rowoff[row] = logf(s);
}

__global__ void logsm_apply_k(float* __restrict__ C) {
    const int row = blockIdx.y;
    const int i = blockIdx.x * blockDim.x + threadIdx.x;
    if (i >= VV/4) return;
    float4* p = (float4*)(C + (size_t)row * VV);
    float off = __ldg(&g_rowoff[row]);
    float4 v = p[i];
    v.x -= off; v.y -= off; v.z -= off; v.w -= off;
    p[i] = v;
}

// ---------------- launcher ----------------------------------------------------
extern "C" void kernel_launch(void* const* d_in, const int* in_sizes, int n_in,
                              void* d_out, int out_size) {
    const int*   token_idx = (const int*)  d_in[0];
    const float* X     = (const float*)d_in[1];
    const float* W_ih0 = (const float*)d_in[2];
    const float* W_hh0 = (const float*)d_in[3];
    const float* b0    = (const float*)d_in[4];
    const float* W_ih1 = (const float*)d_in[5];
    const float* W_hh1 = (const float*)d_in[6];
    const float* b1    = (const float*)d_in[7];
    const float* W_out = (const float*)d_in[8];
    const float* b_out = (const float*)d_in[9];
    float* out = (float*)d_out;

    cudaFuncSetAttribute(gemm_bf16_k,
                         cudaFuncAttributeMaxDynamicSharedMemorySize, GEMM_SMEM);

    void *p_emb, *p_Wih0, *p_Wout, *p_xg, *p_h1, *p_ps;
    cudaGetSymbolAddress(&p_emb,  g_emb);
    cudaGetSymbolAddress(&p_Wih0, g_Wih0);
    cudaGetSymbolAddress(&p_Wout, g_Wout);
    cudaGetSymbolAddress(&p_xg,   g_xg);
    cudaGetSymbolAddress(&p_h1,   g_h1);
    cudaGetSymbolAddress(&p_ps,   g_psum);

    // layer-0 input GEMM inputs
    gather_embed_k<<<(MROWS*(DD/4) + 255)/256, 256>>>(token_idx, X);
    f32_to_bf16_k<<<(G4H*DD/4 + 255)/256, 256>>>(W_ih0, (__nv_bfloat16*)p_Wih0, G4H*DD/4);
    // big W_out conversion (independent of everything else)
    f32_to_bf16_k<<<(VV*HH/4 + 255)/256, 256>>>(W_out, (__nv_bfloat16*)p_Wout, VV*HH/4);

    gemm_bf16_k<<<dim3(MROWS/128, G4H/128), 256, GEMM_SMEM>>>(
        (const __nv_bfloat16*)p_emb, (const __nv_bfloat16*)p_Wih0, b0,
        (float*)p_xg, MROWS, G4H, DD, (float*)p_ps, 0);

    // fused 2-layer recurrence (layer-1 input GEMM folded in)
    lstm_fused_k<<<NB_REC, 256>>>(
        (const float*)p_xg, W_hh0, W_ih1, b1, W_hh1, (__nv_bfloat16*)p_h1);

    // output projection (+ fused poly-exp row sums) + log-softmax
    gemm_bf16_k<<<dim3(MROWS/128, NTILE), 256, GEMM_SMEM>>>(
        (const __nv_bfloat16*)p_h1, (const __nv_bfloat16*)p_Wout, b_out,
        out, MROWS, VV, HH, (float*)p_ps, 1);
    rowlog_k<<<MROWS/8, 256>>>((const float*)p_ps);
    logsm_apply_k<<<dim3((VV/4 + 255)/256, MROWS), 256>>>(out);
}

// round 16
// speedup vs baseline: 1.6666x; 1.0201x over previous
#include <cuda_runtime.h>
#include <cuda_bf16.h>
#include <cstdint>
#include <math.h>

// Problem constants
#define BB 4
#define TT 512
#define DD 512
#define HH 1024
#define VV 50000
#define VPAD 50048             // VV rounded up to 128
#define NTILE (VPAD/128)       // 391 n-tiles in the V GEMM
#define PSPITCH 392            // partial-sum row pitch
#define MROWS (BB*TT)          // 2048
#define G4H (4*HH)             // 4096
#define NB_REC 128             // recurrence CTAs (all resident wave-1)
#define NCHUNK 16              // h broadcast chunks per step (64 cols each)
#define CPC 8                  // CTAs per chunk
#define CNT_TARGET CPC         // ONE release per producer CTA (warp-collective)
#define HSP 136                // hstage bf16 row pitch (bank-conflict-light)

// ---------------- device scratch (static; zero-initialized) ------------------
__device__ __align__(256) __nv_bfloat16 g_emb [MROWS*DD];
__device__ __align__(256) __nv_bfloat16 g_Wih0[G4H*DD];
__device__ __align__(256) __nv_bfloat16 g_Wout[(size_t)VPAD*HH];  // tail rows stay 0
__device__ __align__(256) float         g_xg  [MROWS*G4H];
__device__ __align__(256) __nv_bfloat16 g_h1  [MROWS*HH];
__device__ __align__(256) __nv_bfloat16 g_h0buf[2*BB*HH];         // bf16 h0 exchange
__device__ __align__(256) __nv_bfloat16 g_h1buf[2*BB*HH];         // bf16 h1 exchange
__device__ __align__(256) int           g_cnt0[TT][NCHUNK][32];   // counter @[..][0]
__device__ __align__(256) int           g_cnt1[TT][NCHUNK][32];
__device__ __align__(256) float         g_psum[(size_t)MROWS*PSPITCH];
__device__ __align__(256) float         g_rowoff[MROWS];

// ---------------- small helpers ----------------------------------------------
__device__ __forceinline__ uint32_t smem_u32(const void* p) {
    return (uint32_t)__cvta_generic_to_shared(p);
}
__device__ __forceinline__ void ldmatrix_x4(uint32_t r[4], uint32_t addr) {
    asm volatile("ldmatrix.sync.aligned.m8n8.x4.shared.b16 {%0,%1,%2,%3}, [%4];"
                 : "=r"(r[0]), "=r"(r[1]), "=r"(r[2]), "=r"(r[3]) : "r"(addr));
}
__device__ __forceinline__ void mma16816(float d[4], const uint32_t a[4],
                                         const uint32_t b[2], const float c[4]) {
    asm volatile(
        "mma.sync.aligned.m16n8k16.row.col.f32.bf16.bf16.f32 "
        "{%0,%1,%2,%3}, {%4,%5,%6,%7}, {%8,%9}, {%10,%11,%12,%13};"
        : "=f"(d[0]), "=f"(d[1]), "=f"(d[2]), "=f"(d[3])
        : "r"(a[0]), "r"(a[1]), "r"(a[2]), "r"(a[3]),
          "r"(b[0]), "r"(b[1]),
          "f"(c[0]), "f"(c[1]), "f"(c[2]), "f"(c[3]));
}
__device__ __forceinline__ void cp_async16(uint32_t saddr, const void* g) {
    asm volatile("cp.async.cg.shared.global [%0], [%1], 16;" :: "r"(saddr), "l"(g));
}
__device__ __forceinline__ void cp_commit() {
    asm volatile("cp.async.commit_group;");
}
__device__ __forceinline__ int ld_acq(const int* p) {
    int v;
    asm volatile("ld.acquire.gpu.global.b32 %0, [%1];" : "=r"(v) : "l"(p) : "memory");
    return v;
}
__device__ __forceinline__ void red_rel_add(int* p) {
    int one = 1;
    asm volatile("red.release.gpu.global.add.s32 [%0], %1;" :: "l"(p), "r"(one) : "memory");
}
__device__ __forceinline__ float tanhapx(float x) {
    float y; asm("tanh.approx.f32 %0, %1;" : "=f"(y) : "f"(x)); return y;
}
__device__ __forceinline__ float sigapx(float x) {
    return fmaf(0.5f, tanhapx(0.5f * x), 0.5f);
}
__device__ __forceinline__ uint32_t pack_bf2(float x, float y) {
    __nv_bfloat162 b = __floats2bfloat162_rn(x, y);   // .x in low half
    return *(uint32_t*)&b;
}
__device__ __forceinline__ uint32_t lds_u32(uint32_t addr) {
    uint32_t v;
    asm volatile("ld.shared.b32 %0, [%1];" : "=r"(v) : "r"(addr));
    return v;
}
// exp(x) for |x| << 1: degree-4 Taylor (pure FFMA, no MUFU)
__device__ __forceinline__ float pexp(float x) {
    float p = fmaf(x, 0.041666667f, 0.166666667f);
    p = fmaf(x, p, 0.5f);
    p = fmaf(x, p, 1.0f);
    return fmaf(x, p, 1.0f);
}

// ---------------- conversion / gather kernels ---------------------------------
__global__ void f32_to_bf16_k(const float* __restrict__ in,
                              __nv_bfloat16* __restrict__ out, int n4) {
    int i = blockIdx.x * blockDim.x + threadIdx.x;
    if (i >= n4) return;
    float4 v = *((const float4*)in + i);
    __nv_bfloat162 lo = __floats2bfloat162_rn(v.x, v.y);
    __nv_bfloat162 hi = __floats2bfloat162_rn(v.z, v.w);
    uint2 u;
    u.x = *(uint32_t*)&lo; u.y = *(uint32_t*)&hi;
    *((uint2*)out + i) = u;
}

__global__ void gather_embed_k(const int* __restrict__ idx,
                               const float* __restrict__ X) {
    int i = blockIdx.x * blockDim.x + threadIdx.x;   // one float4 each
    if (i >= MROWS * (DD/4)) return;
    int r = i >> 7;             // DD/4 = 128
    int j = i & 127;
    int tok = __ldg(&idx[r]);
    float4 v = *(const float4*)(X + (size_t)tok * DD + j * 4);
    __nv_bfloat162 lo = __floats2bfloat162_rn(v.x, v.y);
    __nv_bfloat162 hi = __floats2bfloat162_rn(v.z, v.w);
    uint2 u; u.x = *(uint32_t*)&lo; u.y = *(uint32_t*)&hi;
    *((uint2*)(g_emb + (size_t)r * DD) + j) = u;
}

// ---------------- bf16 MMA GEMM: C[M,N] = A[M,K] * B[N,K]^T + bias ------------
// CTA tile 128x128, K-tile 64, 3-stage cp.async, SINGLE syncthreads per K-tile
// (wait -> sync -> prefetch kt+2 -> compute), B fragments via paired
// ldmatrix.x4. 8 warps (2Mx4N, warp tile 64x32).
// do_sum: also emit per-tile poly-exp row-sums into psum[row*PSPITCH + by].
#define GPITCH 72
#define GSTAGE (128*GPITCH)
#define NSTG 3
#define GEMM_SMEM (NSTG*2*GSTAGE*2)      // bytes = 110592

__global__ __launch_bounds__(256) void gemm_bf16_k(
    const __nv_bfloat16* __restrict__ A, const __nv_bfloat16* __restrict__ B,
    const float* __restrict__ bias, float* __restrict__ C,
    int M, int N, int K, float* __restrict__ psum, int do_sum)
{
    extern __shared__ __nv_bfloat16 gsm_[];

    const int tid  = threadIdx.x;
    const int warp = tid >> 5, lane = tid & 31;
    const int wm = warp & 1, wn = warp >> 1;
    const int m0 = blockIdx.x * 128, n0 = blockIdx.y * 128;

    float acc[4][4][4];
#pragma unroll
    for (int a = 0; a < 4; a++)
#pragma unroll
        for (int b = 0; b < 4; b++)
#pragma unroll
            for (int c = 0; c < 4; c++) acc[a][b][c] = 0.f;

    const int ktiles = K >> 6;

    auto load_stage = [&](int st, int k0) {
        __nv_bfloat16* sA = gsm_ + st * 2 * GSTAGE;
        __nv_bfloat16* sB = sA + GSTAGE;
#pragma unroll
        for (int i = 0; i < 4; i++) {
            int c   = tid + i * 256;
            int row = c >> 3;
            int col = (c & 7) << 3;
            cp_async16(smem_u32(sA + row*GPITCH + col),
                       A + (size_t)(m0 + row) * K + k0 + col);
            cp_async16(smem_u32(sB + row*GPITCH + col),
                       B + (size_t)(n0 + row) * K + k0 + col);
        }
    };

    load_stage(0, 0);
    cp_commit();
    if (ktiles > 1) { load_stage(1, 64); cp_commit(); }

    for (int kt = 0; kt < ktiles; kt++) {
        // wait for tile kt (tile kt+1 may remain pending)
        if (kt + 1 < ktiles) asm volatile("cp.async.wait_group 1;");
        else                 asm volatile("cp.async.wait_group 0;");
        __syncthreads();   // also guards: reads of stage kt-1 finished before
                           // its buffer (stage (kt+2)%3) is rewritten below

        if (kt + 2 < ktiles) {
            int st2 = kt + 2; while (st2 >= NSTG) st2 -= NSTG;
            load_stage(st2, (kt + 2) << 6);
            cp_commit();
        }

        int st = kt; while (st >= NSTG) st -= NSTG;
        const __nv_bfloat16* cA = gsm_ + st * 2 * GSTAGE;
        const __nv_bfloat16* cB = cA + GSTAGE;
#pragma unroll
        for (int ks = 0; ks < 4; ks++) {
            uint32_t af[4][4], bf[4][2];
#pragma unroll
            for (int mt = 0; mt < 4; mt++) {
                uint32_t addr = smem_u32(
                    cA + (wm*64 + mt*16 + (lane & 15))*GPITCH
                       + ks*16 + ((lane >> 4) << 3));
                ldmatrix_x4(af[mt], addr);
            }
#pragma unroll
            for (int nt2 = 0; nt2 < 2; nt2++) {
                uint32_t r[4];
                uint32_t addr = smem_u32(
                    cB + (wn*32 + nt2*16 + ((lane >> 4) << 3) + (lane & 7))*GPITCH
                       + ks*16 + (((lane >> 3) & 1) << 3));
                ldmatrix_x4(r, addr);
                bf[2*nt2][0]   = r[0]; bf[2*nt2][1]   = r[1];
                bf[2*nt2+1][0] = r[2]; bf[2*nt2+1][1] = r[3];
            }
#pragma unroll
            for (int mt = 0; mt < 4; mt++)
#pragma unroll
                for (int nt = 0; nt < 4; nt++)
                    mma16816(acc[mt][nt], af[mt], bf[nt], acc[mt][nt]);
        }
        // no trailing sync: next iteration's top sync provides the barrier
    }

    // epilogue: write C (+ optional poly-exp row-sum partials)
    float rs[4][2];
#pragma unroll
    for (int mt = 0; mt < 4; mt++) { rs[mt][0] = 0.f; rs[mt][1] = 0.f; }

#pragma unroll
    for (int mt = 0; mt < 4; mt++)
#pragma unroll
        for (int nt = 0; nt < 4; nt++)
#pragma unroll
            for (int i = 0; i < 4; i++) {
                int row = m0 + wm*64 + mt*16 + (lane >> 2) + ((i >> 1) << 3);
                int col = n0 + wn*32 + nt*8 + ((lane & 3) << 1) + (i & 1);
                if (col < N) {
                    float v = acc[mt][nt][i] + __ldg(&bias[col]);
                    C[(size_t)row * N + col] = v;
                    if (do_sum) rs[mt][i >> 1] += pexp(v);
                }
            }

    if (do_sum) {
        float* ps = (float*)gsm_;            // reuse smem for [4][128] floats
        __syncthreads();                     // all smem-stage reads are done
#pragma unroll
        for (int mt = 0; mt < 4; mt++)
#pragma unroll
            for (int ih = 0; ih < 2; ih++) {
                float s = rs[mt][ih];
                s += __shfl_xor_sync(0xffffffffu, s, 1);
                s += __shfl_xor_sync(0xffffffffu, s, 2);
                if ((lane & 3) == 0) {
                    int rloc = wm*64 + mt*16 + (lane >> 2) + ih*8;
                    ps[wn*128 + rloc] = s;
                }
            }
        __syncthreads();
        if (tid < 128) {
            float s = ps[tid] + ps[128 + tid] + ps[256 + tid] + ps[384 + tid];
            psum[(size_t)(m0 + tid) * PSPITCH + blockIdx.y] = s;
        }
    }
}

// ---------------- fused 2-layer persistent LSTM --------------------------------
// R12 design; publish is now warp-collective: lanes store h, __syncwarp()
// (cumulative ordering), lane0 alone does red.release -> CNT_TARGET = 8.
__global__ __launch_bounds__(256) void lstm_fused_k(
    const float* __restrict__ xg,
    const float* __restrict__ Whh0,
    const float* __restrict__ Wih1,
    const float* __restrict__ b1,
    const float* __restrict__ Whh1,
    __nv_bfloat16* __restrict__ hseq1)
{
    __shared__ __align__(16) __nv_bfloat16 hst0[8][4][HSP];
    __shared__ __align__(16) __nv_bfloat16 hst1[8][4][HSP];
    __shared__ __align__(16) float part0[8*128];
    __shared__ __align__(16) float part1[8*128];
    __shared__ float sxg[2][128];
    __shared__ float csm0[32], csm1[32];

    const int tid  = threadIdx.x;
    const int bk   = blockIdx.x;
    const int c0   = bk * 8;
    const int ke   = tid >> 5;
    const int lane = tid & 31;

    if (bk < NCHUNK && tid == 0) {
        g_cnt0[TT-2][bk][0] = 0; g_cnt0[TT-1][bk][0] = 0;
        g_cnt1[TT-2][bk][0] = 0; g_cnt1[TT-1][bk][0] = 0;
    }

    uint32_t A0[2][8][4], Ai[2][8][4], A1[2][8][4];
    {
        const int r0 = lane >> 2;
        const int kc = (lane & 3) * 2;
#pragma unroll
        for (int mt = 0; mt < 2; mt++) {
#pragma unroll
            for (int kt = 0; kt < 8; kt++) {
                int kg = 128*ke + 16*kt + kc;
                int lrA = 16*mt + r0, lrB = lrA + 8;
                size_t oA = (size_t)((lrA >> 3)*HH + c0 + (lrA & 7)) * HH + kg;
                size_t oB = (size_t)((lrB >> 3)*HH + c0 + (lrB & 7)) * HH + kg;
#define LOADFRAG(W, F) { \
                float2 a0 = __ldg((const float2*)(W + oA)); \
                float2 a1 = __ldg((const float2*)(W + oB)); \
                float2 a2 = __ldg((const float2*)(W + oA + 8)); \
                float2 a3 = __ldg((const float2*)(W + oB + 8)); \
                F[mt][kt][0] = pack_bf2(a0.x, a0.y); \
                F[mt][kt][1] = pack_bf2(a1.x, a1.y); \
                F[mt][kt][2] = pack_bf2(a2.x, a2.y); \
                F[mt][kt][3] = pack_bf2(a3.x, a3.y); }
                LOADFRAG(Whh0, A0)
                LOADFRAG(Wih1, Ai)
                LOADFRAG(Whh1, A1)
#undef LOADFRAG
            }
        }
    }
    if (tid < 32) { csm0[tid] = 0.f; csm1[tid] = 0.f; }

    float b1v[4];
    {
        int cc = lane >> 2;
#pragma unroll
        for (int g = 0; g < 4; g++) b1v[g] = __ldg(&b1[g*HH + c0 + cc]);
    }

    const int lrx = tid >> 2, bx = tid & 3;
    const float* xgp = xg + (size_t)bx*TT*G4H + (lrx >> 3)*HH + c0 + (lrx & 7);

    const int  bsel = (lane >> 2) & 3;
    const bool bval = lane < 16;
    const uint32_t hb0 = smem_u32(&hst0[ke][bsel][0]) + (lane & 3) * 4;
    const uint32_t hb1 = smem_u32(&hst1[ke][bsel][0]) + (lane & 3) * 4;
    const int sb = lane >> 3, sj = (lane & 7) * 8;

    const int grp = lane >> 3;
    const int chp = 2*ke + (grp & 1);

    __syncthreads();

    for (int s = 0; s <= TT; s++) {
        if (tid < 128 && s < TT) sxg[s & 1][tid] = __ldg(xgp + (size_t)s * G4H);

        float acc0[8] = {0,0,0,0,0,0,0,0};
        float acc1[8] = {0,0,0,0,0,0,0,0};

        if (s > 0) {
            const __nv_bfloat16* h0src = g_h0buf + (s & 1) * BB * HH;
            const __nv_bfloat16* h1src = g_h1buf + (s & 1) * BB * HH;

            {   // ONE combined poll of all 4 chunk counters (lane-groups)
                const int* cp = (grp < 2) ? &g_cnt0[s-1][chp][0]
                                          : &g_cnt1[s-1][chp][0];
                int ok;
                do { ok = (ld_acq(cp) >= CNT_TARGET); }
                while (__ballot_sync(0xffffffffu, ok) != 0xffffffffu);
            }

            // stage all 4 chunks back-to-back (MLP = 4)
            uint4 v00 = __ldcg((const uint4*)(h0src + sb*HH + 128*ke +      sj));
            uint4 v01 = __ldcg((const uint4*)(h0src + sb*HH + 128*ke + 64 + sj));
            uint4 v10 = __ldcg((const uint4*)(h1src + sb*HH + 128*ke +      sj));
            uint4 v11 = __ldcg((const uint4*)(h1src + sb*HH + 128*ke + 64 + sj));
            *(uint4*)&hst0[ke][sb][     sj] = v00;
            *(uint4*)&hst0[ke][sb][64 + sj] = v01;
            *(uint4*)&hst1[ke][sb][     sj] = v10;
            *(uint4*)&hst1[ke][sb][64 + sj] = v11;
            __syncwarp();

#pragma unroll
            for (int kq = 0; kq < 8; kq++) {
                uint32_t addr = hb0 + (16*kq) * 2;
                uint32_t bf[2];
                bf[0] = bval ? lds_u32(addr)      : 0u;
                bf[1] = bval ? lds_u32(addr + 16) : 0u;
                mma16816(acc0,     A0[0][kq], bf, acc0);
                mma16816(acc0 + 4, A0[1][kq], bf, acc0 + 4);
                mma16816(acc1,     Ai[0][kq], bf, acc1);
                mma16816(acc1 + 4, Ai[1][kq], bf, acc1 + 4);
            }
#pragma unroll
            for (int kq = 0; kq < 8; kq++) {
                uint32_t addr = hb1 + (16*kq) * 2;
                uint32_t bf[2];
                bf[0] = bval ? lds_u32(addr)      : 0u;
                bf[1] = bval ? lds_u32(addr + 16) : 0u;
                mma16816(acc1,     A1[0][kq], bf, acc1);
                mma16816(acc1 + 4, A1[1][kq], bf, acc1 + 4);
            }

            if (s >= 2 && bk < NCHUNK && tid == 32) {
                g_cnt0[s-2][bk][0] = 0;
                g_cnt1[s-2][bk][0] = 0;
            }
        }

        if ((lane & 3) < 2) {
            int r0 = lane >> 2, bc = (lane & 3) * 2;
#pragma unroll
            for (int mt = 0; mt < 2; mt++) {
                *(float2*)&part0[ke*128 + (mt*16 + r0    )*4 + bc] = make_float2(acc0[mt*4+0], acc0[mt*4+1]);
                *(float2*)&part0[ke*128 + (mt*16 + r0 + 8)*4 + bc] = make_float2(acc0[mt*4+2], acc0[mt*4+3]);
                *(float2*)&part1[ke*128 + (mt*16 + r0    )*4 + bc] = make_float2(acc1[mt*4+0], acc1[mt*4+1]);
                *(float2*)&part1[ke*128 + (mt*16 + r0 + 8)*4 + bc] = make_float2(acc1[mt*4+2], acc1[mt*4+3]);
            }
        }
        __syncthreads();                     // the ONLY CTA-wide sync per wave

        if (tid < 32 && s < TT) {
            // warp0: layer0 tail -> h0[s]
            int cc = tid >> 2, b = tid & 3;
            float g4[4];
#pragma unroll
            for (int g = 0; g < 4; g++) {
                int rr = g*8 + cc;
                float sum = sxg[s & 1][rr*4 + b];
#pragma unroll
                for (int k8 = 0; k8 < 8; k8++) sum += part0[k8*128 + rr*4 + b];
                g4[g] = sum;
            }
            float iv = sigapx(g4[0]), fv = sigapx(g4[1]);
            float gv = tanhapx(g4[2]), ov = sigapx(g4[3]);
            float c = fv * csm0[tid] + iv * gv;
            csm0[tid] = c;
            float h = ov * tanhapx(c);
            g_h0buf[((s + 1) & 1) * BB * HH + b * HH + c0 + cc] = __float2bfloat16(h);
            __syncwarp();                         // order all lanes' h stores
            if (lane == 0) red_rel_add(&g_cnt0[s][bk >> 3][0]);
        } else if (tid >= 32 && tid < 64) {
            // warp1: layer1 tail -> h1[s-1]
            int cc = lane >> 2, b = lane & 3;
            if (s > 0) {
                float g4[4];
#pragma unroll
                for (int g = 0; g < 4; g++) {
                    int rr = g*8 + cc;
                    float sum = b1v[g];
#pragma unroll
                    for (int k8 = 0; k8 < 8; k8++) sum += part1[k8*128 + rr*4 + b];
                    g4[g] = sum;
                }
                float iv = sigapx(g4[0]), fv = sigapx(g4[1]);
                float gv = tanhapx(g4[2]), ov = sigapx(g4[3]);
                float c = fv * csm1[lane] + iv * gv;
                csm1[lane] = c;
                float h = ov * tanhapx(c);
                __nv_bfloat16 hb = __float2bfloat16(h);
                g_h1buf[((s + 1) & 1) * BB * HH + b * HH + c0 + cc] = hb;
                __syncwarp();
                if (lane == 0 && s < TT) red_rel_add(&g_cnt1[s][bk >> 3][0]);
                hseq1[(size_t)(b*TT + (s-1)) * HH + c0 + cc] = hb;
            } else {
                g_h1buf[1 * BB * HH + b * HH + c0 + cc] = __float2bfloat16(0.f);
                __syncwarp();
                if (lane == 0) red_rel_add(&g_cnt1[0][bk >> 3][0]);
            }
        }
    }
}

// ---------------- log-softmax tail ---------------------------------------------
__global__ void rowlog_k(const float* __restrict__ ps) {
    int row  = blockIdx.x * 8 + (threadIdx.x >> 5);
    int lane = threadIdx.x & 31;
    const float* p = ps + (size_t)row * PSPITCH;
    float s = 0.f;
    for (int i = lane; i < PSPITCH; i += 32) s += p[i];   // pad entry is 0
#pragma unroll
    for (int m = 16; m > 0; m >>= 1) s += __shfl_xor_sync(0xffffffffu, s, m);
    if (lane == 0) g_rowoff[row] = logf(s);
}

__global__ void logsm_apply_k(float* __restrict__ C) {
    const int row = blockIdx.y;
    const int i = blockIdx.x * blockDim.x + threadIdx.x;
    if (i >= VV/4) return;
    float4* p = (float4*)(C + (size_t)row * VV);
    float off = __ldg(&g_rowoff[row]);
    float4 v = p[i];
    v.x -= off; v.y -= off; v.z -= off; v.w -= off;
    p[i] = v;
}

// ---------------- launcher ----------------------------------------------------
extern "C" void kernel_launch(void* const* d_in, const int* in_sizes, int n_in,
                              void* d_out, int out_size) {
    const int*   token_idx = (const int*)  d_in[0];
    const float* X     = (const float*)d_in[1];
    const float* W_ih0 = (const float*)d_in[2];
    const float* W_hh0 = (const float*)d_in[3];
    const float* b0    = (const float*)d_in[4];
    const float* W_ih1 = (const float*)d_in[5];
    const float* W_hh1 = (const float*)d_in[6];
    const float* b1    = (const float*)d_in[7];
    const float* W_out = (const float*)d_in[8];
    const float* b_out = (const float*)d_in[9];
    float* out = (float*)d_out;

    cudaFuncSetAttribute(gemm_bf16_k,
                         cudaFuncAttributeMaxDynamicSharedMemorySize, GEMM_SMEM);

    void *p_emb, *p_Wih0, *p_Wout, *p_xg, *p_h1, *p_ps;
    cudaGetSymbolAddress(&p_emb,  g_emb);
    cudaGetSymbolAddress(&p_Wih0, g_Wih0);
    cudaGetSymbolAddress(&p_Wout, g_Wout);
    cudaGetSymbolAddress(&p_xg,   g_xg);
    cudaGetSymbolAddress(&p_h1,   g_h1);
    cudaGetSymbolAddress(&p_ps,   g_psum);

    // layer-0 input GEMM inputs
    gather_embed_k<<<(MROWS*(DD/4) + 255)/256, 256>>>(token_idx, X);
    f32_to_bf16_k<<<(G4H*DD/4 + 255)/256, 256>>>(W_ih0, (__nv_bfloat16*)p_Wih0, G4H*DD/4);
    // big W_out conversion (independent of everything else)
    f32_to_bf16_k<<<(VV*HH/4 + 255)/256, 256>>>(W_out, (__nv_bfloat16*)p_Wout, VV*HH/4);

    gemm_bf16_k<<<dim3(MROWS/128, G4H/128), 256, GEMM_SMEM>>>(
        (const __nv_bfloat16*)p_emb, (const __nv_bfloat16*)p_Wih0, b0,
        (float*)p_xg, MROWS, G4H, DD, (float*)p_ps, 0);

    // fused 2-layer recurrence (layer-1 input GEMM folded in)
    lstm_fused_k<<<NB_REC, 256>>>(
        (const float*)p_xg, W_hh0, W_ih1, b1, W_hh1, (__nv_bfloat16*)p_h1);

    // output projection (+ fused poly-exp row sums) + log-softmax
    gemm_bf16_k<<<dim3(MROWS/128, NTILE), 256, GEMM_SMEM>>>(
        (const __nv_bfloat16*)p_h1, (const __nv_bfloat16*)p_Wout, b_out,
        out, MROWS, VV, HH, (float*)p_ps, 1);
    rowlog_k<<<MROWS/8, 256>>>((const float*)p_ps);
    logsm_apply_k<<<dim3((VV/4 + 255)/256, MROWS), 256>>>(out);
}